// round 5
// baseline (speedup 1.0000x reference)
#include <cuda_runtime.h>
#include <cuda_bf16.h>
#include <math.h>
#include <stdint.h>

#define B_   2
#define S_   2048
#define D_   2048
#define H_   16
#define KVH_ 8
#define HD_  128
#define M_   (B_ * S_)          // 4096
#define NQ_  (H_ * HD_)         // 2048
#define NKV_ (KVH_ * HD_)       // 1024
#define REP_ (H_ / KVH_)        // 2
#define EPS_ 1e-6f

// ---------------- scratch (device globals, allocation-free) ----------------
__device__ __align__(256) float g_qproj[M_ * NQ_];
__device__ __align__(256) float g_kproj[M_ * NKV_];
__device__ __align__(256) float g_vproj[M_ * NKV_];
__device__ __align__(256) float g_att[M_ * NQ_];
// int8 activation planes + row scales
__device__ __align__(256) int8_t g_x8h[M_ * D_];
__device__ __align__(256) int8_t g_x8l[M_ * D_];
__device__ __align__(256) float  g_xs[M_];
__device__ __align__(256) int8_t g_a8h[M_ * NQ_];
__device__ __align__(256) int8_t g_a8l[M_ * NQ_];
__device__ __align__(256) float  g_as[M_];
// int8 weights
__device__ __align__(256) int8_t g_w8q[NQ_ * D_];
__device__ __align__(256) int8_t g_w8k[NKV_ * D_];
__device__ __align__(256) int8_t g_w8v[NKV_ * D_];
__device__ __align__(256) int8_t g_w8o[D_ * NQ_];
// attention operands, bf16 hi/lo
__device__ __align__(256) __nv_bfloat16 g_Qhi[M_ * NQ_];
__device__ __align__(256) __nv_bfloat16 g_Qlo[M_ * NQ_];
__device__ __align__(256) __nv_bfloat16 g_Khi[M_ * NKV_];
__device__ __align__(256) __nv_bfloat16 g_Klo[M_ * NKV_];
__device__ __align__(256) __nv_bfloat16 g_Vhi[M_ * NKV_];
__device__ __align__(256) __nv_bfloat16 g_Vlo[M_ * NKV_];

// ---------------- PTX helpers (baseline PTX only) ----------------
__device__ __forceinline__ uint32_t smem_u32(const void* p) {
    uint32_t a;
    asm("{ .reg .u64 t; cvta.to.shared.u64 t, %1; cvt.u32.u64 %0, t; }" : "=r"(a) : "l"(p));
    return a;
}
__device__ __forceinline__ void cp16(uint32_t s, const void* g) {
    asm volatile("cp.async.cg.shared.global [%0], [%1], 16;" :: "r"(s), "l"(g));
}
#define CP_COMMIT() asm volatile("cp.async.commit_group;" ::: "memory")
#define CP_WAIT(n)  asm volatile("cp.async.wait_group %0;" :: "n"(n) : "memory")

__device__ __forceinline__ void ldm4(uint32_t* r, uint32_t addr) {
    asm volatile("ldmatrix.sync.aligned.m8n8.x4.shared.b16 {%0,%1,%2,%3}, [%4];"
                 : "=r"(r[0]), "=r"(r[1]), "=r"(r[2]), "=r"(r[3]) : "r"(addr));
}
__device__ __forceinline__ void ldm4t(uint32_t* r, uint32_t addr) {
    asm volatile("ldmatrix.sync.aligned.m8n8.x4.trans.shared.b16 {%0,%1,%2,%3}, [%4];"
                 : "=r"(r[0]), "=r"(r[1]), "=r"(r[2]), "=r"(r[3]) : "r"(addr));
}
__device__ __forceinline__ void mma16816(float* c, const uint32_t* a, const uint32_t* b) {
    asm volatile("mma.sync.aligned.m16n8k16.row.col.f32.bf16.bf16.f32 "
                 "{%0,%1,%2,%3}, {%4,%5,%6,%7}, {%8,%9}, {%0,%1,%2,%3};"
                 : "+f"(c[0]), "+f"(c[1]), "+f"(c[2]), "+f"(c[3])
                 : "r"(a[0]), "r"(a[1]), "r"(a[2]), "r"(a[3]), "r"(b[0]), "r"(b[1]));
}
__device__ __forceinline__ void imma16832(int* c, const uint32_t* a, const uint32_t* b) {
    asm volatile("mma.sync.aligned.m16n8k32.row.col.s32.s8.s8.s32 "
                 "{%0,%1,%2,%3}, {%4,%5,%6,%7}, {%8,%9}, {%0,%1,%2,%3};"
                 : "+r"(c[0]), "+r"(c[1]), "+r"(c[2]), "+r"(c[3])
                 : "r"(a[0]), "r"(a[1]), "r"(a[2]), "r"(a[3]), "r"(b[0]), "r"(b[1]));
}

// swizzles: 128B rows and 256B rows
__device__ __forceinline__ uint32_t sw128(uint32_t off) { return off ^ ((off >> 3) & 0x70); }
__device__ __forceinline__ uint32_t sw256(uint32_t off) { return off ^ ((off >> 4) & 0x70); }

// split fp32 pair -> bf16x2 hi + lo
__device__ __forceinline__ void split2(float a, float b, uint32_t& hi, uint32_t& lo) {
    __nv_bfloat162 h = __floats2bfloat162_rn(a, b);
    float ra = a - __bfloat162float(h.x);
    float rb = b - __bfloat162float(h.y);
    __nv_bfloat162 l = __floats2bfloat162_rn(ra, rb);
    hi = *(uint32_t*)&h;
    lo = *(uint32_t*)&l;
}

// ---------------- quantization kernels ----------------
// per-row int16 quantization split into two int8 planes; K = 2048 fixed
__global__ __launch_bounds__(256)
void quant_rows(const float* __restrict__ X, int8_t* __restrict__ hi,
                int8_t* __restrict__ lo, float* __restrict__ sc) {
    const int row = blockIdx.x;
    const int t = threadIdx.x;
    const float* xr = X + (size_t)row * 2048;
    float4 v0 = ((const float4*)xr)[2 * t];
    float4 v1 = ((const float4*)xr)[2 * t + 1];
    float a[8] = {v0.x, v0.y, v0.z, v0.w, v1.x, v1.y, v1.z, v1.w};
    float mx = 0.0f;
    #pragma unroll
    for (int j = 0; j < 8; j++) mx = fmaxf(mx, fabsf(a[j]));
    #pragma unroll
    for (int o = 16; o > 0; o >>= 1) mx = fmaxf(mx, __shfl_xor_sync(0xffffffffu, mx, o));
    __shared__ float red[8];
    if ((t & 31) == 0) red[t >> 5] = mx;
    __syncthreads();
    float m = red[0];
    #pragma unroll
    for (int j = 1; j < 8; j++) m = fmaxf(m, red[j]);
    m = fmaxf(m, 1e-20f);
    const float inv = 32512.0f / m;
    uint32_t ph[2] = {0, 0}, pl[2] = {0, 0};
    #pragma unroll
    for (int half = 0; half < 2; half++)
        #pragma unroll
        for (int j = 0; j < 4; j++) {
            int qv = __float2int_rn(a[half * 4 + j] * inv);
            int h = (qv + 128) >> 8;
            int l = qv - (h << 8);
            ph[half] |= (uint32_t)(h & 255) << (8 * j);
            pl[half] |= (uint32_t)(l & 255) << (8 * j);
        }
    ((uint2*)(hi + (size_t)row * 2048))[t] = make_uint2(ph[0], ph[1]);
    ((uint2*)(lo + (size_t)row * 2048))[t] = make_uint2(pl[0], pl[1]);
    if (t == 0) sc[row] = m / 32512.0f;
}

__global__ void cvt_w8(const int* __restrict__ w, int8_t* __restrict__ o) {
    int i = blockIdx.x * blockDim.x + threadIdx.x;
    int4 v = ((const int4*)w)[i];
    uint32_t p = (uint32_t)(v.x & 255) | ((uint32_t)(v.y & 255) << 8) |
                 ((uint32_t)(v.z & 255) << 16) | ((uint32_t)(v.w & 255) << 24);
    ((uint32_t*)o)[i] = p;
}

// ---------------- int8 IMMA GEMM ----------------
// C[m,n] = srow[m] * scale[n] * (256*sum(Ahi*W) + sum(Alo*W)), K = 2048
#define IBK       128                 // K per chunk (128 bytes per row)
#define ICHUNK    (D_ / IBK)          // 16
#define ITILE_B   16384               // 128 rows x 128B
#define ISTAGE_B  (3 * ITILE_B)       // Ahi, Alo, W
#define ISTG      3
#define ISMEM_DYN (ISTG * ISTAGE_B + 1024)

__device__ __forceinline__ void i_load_chunk(
    uint32_t tbase, int buf, int kc,
    const int8_t* __restrict__ Ah, const int8_t* __restrict__ Al,
    const int8_t* __restrict__ W, int bm, int bn, int tid) {
    uint32_t st = tbase + buf * ISTAGE_B;
    const int8_t* Ahp = Ah + (size_t)bm * D_ + kc * IBK;
    const int8_t* Alp = Al + (size_t)bm * D_ + kc * IBK;
    const int8_t* Wp  = W  + (size_t)bn * D_ + kc * IBK;
    #pragma unroll
    for (int t = 0; t < 4; t++) {
        int idx = tid + t * 256;            // 0..1023
        int row = idx >> 3;                 // 0..127
        int seg = idx & 7;                  // 16B segment within 128B row
        uint32_t off = sw128((uint32_t)(row * 128 + seg * 16));
        size_t gofs = (size_t)row * D_ + seg * 16;
        cp16(st + off,               Ahp + gofs);
        cp16(st + ITILE_B + off,     Alp + gofs);
        cp16(st + 2 * ITILE_B + off, Wp + gofs);
    }
    CP_COMMIT();
}

__global__ __launch_bounds__(256, 1)
void gemm_i8(const int8_t* __restrict__ Ah, const int8_t* __restrict__ Al,
             const float* __restrict__ rowsc, const int8_t* __restrict__ W,
             const float* __restrict__ scale, float* __restrict__ C, int N) {
    extern __shared__ char dyns[];
    uint32_t tbase = (smem_u32(dyns) + 1023) & ~1023u;

    const int tid = threadIdx.x;
    const int wid = tid >> 5;
    const int L = tid & 31;
    const int bm = blockIdx.y * 128;
    const int bn = blockIdx.x * 128;
    const int wm = (wid & 3) * 32;
    const int wn = (wid >> 2) * 64;

    i_load_chunk(tbase, 0, 0, Ah, Al, W, bm, bn, tid);
    i_load_chunk(tbase, 1, 1, Ah, Al, W, bm, bn, tid);

    int acc1[2][8][4] = {};
    int acc2[2][8][4] = {};

    const int a_row = (L & 7) + ((L >> 3) & 1) * 8;
    const int a_kb  = (L >> 4) * 16;
    const int b_row = (L & 7) + ((L >> 4) << 3);
    const int b_kb  = ((L >> 3) & 1) * 16;

    int buf = 0;
    for (int kc = 0; kc < ICHUNK; kc++) {
        CP_WAIT(1);
        __syncthreads();
        if (kc + 2 < ICHUNK) {
            int nb = buf + 2; if (nb >= ISTG) nb -= ISTG;
            i_load_chunk(tbase, nb, kc + 2, Ah, Al, W, bm, bn, tid);
        } else {
            CP_COMMIT();
        }

        uint32_t st = tbase + buf * ISTAGE_B;
        #pragma unroll
        for (int ks = 0; ks < 4; ks++) {            // 4 x k32 per chunk
            uint32_t ah[2][4], al[2][4], bb[4][4];
            #pragma unroll
            for (int mi = 0; mi < 2; mi++) {
                uint32_t off = sw128((uint32_t)((wm + mi * 16 + a_row) * 128 + ks * 32 + a_kb));
                ldm4(ah[mi], st + off);
                ldm4(al[mi], st + ITILE_B + off);
            }
            #pragma unroll
            for (int nj = 0; nj < 4; nj++) {
                uint32_t off = sw128((uint32_t)((wn + nj * 16 + b_row) * 128 + ks * 32 + b_kb));
                ldm4(bb[nj], st + 2 * ITILE_B + off);
            }
            #pragma unroll
            for (int mi = 0; mi < 2; mi++)
                #pragma unroll
                for (int j = 0; j < 8; j++) {
                    const uint32_t* bf = &bb[j >> 1][(j & 1) * 2];
                    imma16832(acc1[mi][j], ah[mi], bf);
                    imma16832(acc2[mi][j], al[mi], bf);
                }
        }
        buf++; if (buf >= ISTG) buf = 0;
    }

    const int g = L >> 2;
    const int q = L & 3;
    #pragma unroll
    for (int mi = 0; mi < 2; mi++) {
        int r0 = bm + wm + mi * 16 + g;
        float sr0 = __ldg(&rowsc[r0]);
        float sr1 = __ldg(&rowsc[r0 + 8]);
        #pragma unroll
        for (int j = 0; j < 8; j++) {
            int col = bn + wn + j * 8 + q * 2;
            float s0 = __ldg(&scale[col]);
            float s1 = __ldg(&scale[col + 1]);
            float f0 = fmaf(256.0f, (float)acc1[mi][j][0], (float)acc2[mi][j][0]);
            float f1 = fmaf(256.0f, (float)acc1[mi][j][1], (float)acc2[mi][j][1]);
            float f2 = fmaf(256.0f, (float)acc1[mi][j][2], (float)acc2[mi][j][2]);
            float f3 = fmaf(256.0f, (float)acc1[mi][j][3], (float)acc2[mi][j][3]);
            *(float2*)&C[(size_t)r0 * N + col] = make_float2(f0 * sr0 * s0, f1 * sr0 * s1);
            *(float2*)&C[(size_t)(r0 + 8) * N + col] = make_float2(f2 * sr1 * s0, f3 * sr1 * s1);
        }
    }
}

// ---------------- fused RMSNorm + RoPE + head transpose -> bf16 hi/lo -------
__global__ void norm_rope(const float* __restrict__ qnw, const float* __restrict__ knw,
                          const float* __restrict__ cosc, const float* __restrict__ sinc) {
    const int m = blockIdx.x;
    const int role = blockIdx.y;
    const int d = threadIdx.x;
    const int b = m / S_;
    const int s = m % S_;

    if (role >= 24) {                 // V: pure split + transpose
        int h = role - 24;
        float v = g_vproj[(size_t)m * NKV_ + h * HD_ + d];
        size_t o = ((size_t)(b * KVH_ + h) * S_ + s) * HD_ + d;
        __nv_bfloat16 hv = __float2bfloat16(v);
        g_Vhi[o] = hv;
        g_Vlo[o] = __float2bfloat16(v - __bfloat162float(hv));
        return;
    }

    const float* src;
    const float* nw;
    __nv_bfloat16 *dh, *dl;
    size_t o;
    if (role < 16) {                  // Q
        int h = role;
        src = &g_qproj[(size_t)m * NQ_ + h * HD_];
        nw = qnw;
        o = ((size_t)(b * H_ + h) * S_ + s) * HD_ + d;
        dh = g_Qhi; dl = g_Qlo;
    } else {                          // K
        int h = role - 16;
        src = &g_kproj[(size_t)m * NKV_ + h * HD_];
        nw = knw;
        o = ((size_t)(b * KVH_ + h) * S_ + s) * HD_ + d;
        dh = g_Khi; dl = g_Klo;
    }

    float val = src[d];
    float ss = val * val;
    #pragma unroll
    for (int of = 16; of > 0; of >>= 1) ss += __shfl_xor_sync(0xffffffffu, ss, of);
    __shared__ float wred[4];
    if ((d & 31) == 0) wred[d >> 5] = ss;
    __syncthreads();
    float tot = wred[0] + wred[1] + wred[2] + wred[3];
    float rms = rsqrtf(tot * (1.0f / HD_) + EPS_);

    int dp = (d < 64) ? d + 64 : d - 64;
    float sgn = (d < 64) ? -1.0f : 1.0f;
    float xn = val * rms * nw[d];
    float xp = src[dp] * rms * nw[dp];
    float c = cosc[(size_t)s * HD_ + d];
    float sn = sinc[(size_t)s * HD_ + d];
    float v = xn * c + sgn * xp * sn;
    __nv_bfloat16 hv = __float2bfloat16(v);
    dh[o] = hv;
    dl[o] = __float2bfloat16(v - __bfloat162float(hv));
}

// ---------------- tensor-core flash attention (bf16 hi/lo, causal, GQA) -----
#define BQA 128
#define BKVA 64
#define AQ_BYTES   32768
#define AKV_STAGE  65536
#define ASMEM (2 * AQ_BYTES + 2 * AKV_STAGE)   // 192KB

__device__ __forceinline__ void a_load_kv(uint32_t kvbase, int buf, int kt, int nkv,
                                          size_t kvoff, int tid) {
    if (kt < nkv) {
        int k0 = kt * BKVA;
        uint32_t st = kvbase + buf * AKV_STAGE;
        #pragma unroll
        for (int t = 0; t < 4; t++) {
            int idx = tid + t * 256;
            int row = idx >> 4;
            int ch = idx & 15;
            uint32_t off = sw256((uint32_t)(row * 256 + ch * 16));
            size_t gi = kvoff + (size_t)(k0 + row) * HD_ + ch * 8;
            cp16(st + off,         g_Khi + gi);
            cp16(st + 16384 + off, g_Klo + gi);
            cp16(st + 32768 + off, g_Vhi + gi);
            cp16(st + 49152 + off, g_Vlo + gi);
        }
    }
    CP_COMMIT();
}

__global__ __launch_bounds__(256, 1)
void attn_mma() {
    extern __shared__ char smraw[];
    uint32_t sb = smem_u32(smraw);
    const int tid = threadIdx.x;
    const int wid = tid >> 5;
    const int L = tid & 31;
    const int g = L >> 2;
    const int qd = L & 3;

    const int qt = (int)gridDim.x - 1 - (int)blockIdx.x;
    const int bh = blockIdx.y;
    const int b = bh >> 4;
    const int h = bh & 15;
    const int kvh = h >> 1;
    const int q0 = qt * BQA;
    const int nkv = 2 * qt + 2;
    const int wm = wid * 16;

    const uint32_t Qh_s = sb;
    const uint32_t Ql_s = sb + AQ_BYTES;
    const uint32_t kvbase = sb + 2 * AQ_BYTES;

    const __nv_bfloat16* Qhg = g_Qhi + ((size_t)bh * S_ + q0) * HD_;
    const __nv_bfloat16* Qlg = g_Qlo + ((size_t)bh * S_ + q0) * HD_;
    const size_t kvoff = (size_t)(b * KVH_ + kvh) * S_ * HD_;

    #pragma unroll
    for (int t = 0; t < 8; t++) {
        int idx = tid + t * 256;
        int row = idx >> 4;
        int ch = idx & 15;
        uint32_t off = sw256((uint32_t)(row * 256 + ch * 16));
        size_t gi = (size_t)row * HD_ + ch * 8;
        cp16(Qh_s + off, Qhg + gi);
        cp16(Ql_s + off, Qlg + gi);
    }
    a_load_kv(kvbase, 0, 0, nkv, kvoff, tid);
    a_load_kv(kvbase, 1, 1, nkv, kvoff, tid);

    float m0 = -1e30f, m1 = -1e30f, l0 = 0.0f, l1 = 0.0f;
    float oa[16][4] = {};
    const float sc = 0.08838834764831845f;

    for (int kt = 0; kt < nkv; kt++) {
        CP_WAIT(1);
        __syncthreads();
        const int k0 = kt * BKVA;
        const int buf = kt & 1;
        if (k0 <= q0 + wm + 15) {
            uint32_t st = kvbase + buf * AKV_STAGE;
            uint32_t Kh = st, Kl = st + 16384, Vh = st + 32768, Vl = st + 49152;

            float sa[8][4] = {};
            const uint32_t a_part = (uint32_t)((L & 15) * 256 + ((L >> 4) << 4));
            const uint32_t b_row  = (uint32_t)((L & 7) + ((L >> 4) << 3));
            const uint32_t b_kb   = (uint32_t)(((L >> 3) & 1) * 16);
            #pragma unroll
            for (int k16 = 0; k16 < 8; k16++) {
                uint32_t qh[4], ql[4];
                uint32_t aoff = sw256((uint32_t)(wm * 256 + k16 * 32) + a_part);
                ldm4(qh, Qh_s + aoff);
                ldm4(ql, Ql_s + aoff);
                #pragma unroll
                for (int n16 = 0; n16 < 4; n16++) {
                    uint32_t boff = sw256((uint32_t)((n16 * 16 + b_row) * 256 + k16 * 32 + b_kb));
                    uint32_t kh4[4], kl4[4];
                    ldm4(kh4, Kh + boff);
                    ldm4(kl4, Kl + boff);
                    mma16816(sa[n16 * 2],     qh, &kh4[0]);
                    mma16816(sa[n16 * 2 + 1], qh, &kh4[2]);
                    mma16816(sa[n16 * 2],     ql, &kh4[0]);
                    mma16816(sa[n16 * 2 + 1], ql, &kh4[2]);
                    mma16816(sa[n16 * 2],     qh, &kl4[0]);
                    mma16816(sa[n16 * 2 + 1], qh, &kl4[2]);
                }
            }

            const int r0 = q0 + wm + g;
            const int r1 = r0 + 8;
            const bool needmask = (k0 + 63 > q0 + wm);
            #pragma unroll
            for (int t = 0; t < 8; t++) {
                #pragma unroll
                for (int c = 0; c < 4; c++) {
                    float v = sa[t][c] * sc;
                    if (needmask) {
                        int col = k0 + t * 8 + 2 * qd + (c & 1);
                        int row = (c < 2) ? r0 : r1;
                        if (col > row) v = -1e30f;
                    }
                    sa[t][c] = v;
                }
            }

            float mx0 = -1e30f, mx1 = -1e30f;
            #pragma unroll
            for (int t = 0; t < 8; t++) {
                mx0 = fmaxf(mx0, fmaxf(sa[t][0], sa[t][1]));
                mx1 = fmaxf(mx1, fmaxf(sa[t][2], sa[t][3]));
            }
            mx0 = fmaxf(mx0, __shfl_xor_sync(0xffffffffu, mx0, 1));
            mx0 = fmaxf(mx0, __shfl_xor_sync(0xffffffffu, mx0, 2));
            mx1 = fmaxf(mx1, __shfl_xor_sync(0xffffffffu, mx1, 1));
            mx1 = fmaxf(mx1, __shfl_xor_sync(0xffffffffu, mx1, 2));
            float nm0 = fmaxf(m0, mx0), nm1 = fmaxf(m1, mx1);
            float al0 = __expf(m0 - nm0), al1 = __expf(m1 - nm1);
            m0 = nm0; m1 = nm1;
            float rs0 = 0.0f, rs1 = 0.0f;
            #pragma unroll
            for (int t = 0; t < 8; t++) {
                float p0 = __expf(sa[t][0] - m0);
                float p1 = __expf(sa[t][1] - m0);
                float p2 = __expf(sa[t][2] - m1);
                float p3 = __expf(sa[t][3] - m1);
                sa[t][0] = p0; sa[t][1] = p1; sa[t][2] = p2; sa[t][3] = p3;
                rs0 += p0 + p1; rs1 += p2 + p3;
            }
            rs0 += __shfl_xor_sync(0xffffffffu, rs0, 1);
            rs0 += __shfl_xor_sync(0xffffffffu, rs0, 2);
            rs1 += __shfl_xor_sync(0xffffffffu, rs1, 1);
            rs1 += __shfl_xor_sync(0xffffffffu, rs1, 2);
            l0 = l0 * al0 + rs0;
            l1 = l1 * al1 + rs1;
            #pragma unroll
            for (int nt = 0; nt < 16; nt++) {
                oa[nt][0] *= al0; oa[nt][1] *= al0;
                oa[nt][2] *= al1; oa[nt][3] *= al1;
            }

            const uint32_t v_row = (uint32_t)((L & 7) + ((L >> 3) & 1) * 8);
            const uint32_t v_cb  = (uint32_t)((L >> 4) << 4);
            #pragma unroll
            for (int kk = 0; kk < 4; kk++) {
                const int t0 = 2 * kk, t1 = t0 + 1;
                uint32_t ph[4], pl[4];
                split2(sa[t0][0], sa[t0][1], ph[0], pl[0]);
                split2(sa[t0][2], sa[t0][3], ph[1], pl[1]);
                split2(sa[t1][0], sa[t1][1], ph[2], pl[2]);
                split2(sa[t1][2], sa[t1][3], ph[3], pl[3]);
                #pragma unroll
                for (int n16 = 0; n16 < 8; n16++) {
                    uint32_t voff = sw256((uint32_t)((kk * 16 + v_row) * 256 + n16 * 32) + v_cb);
                    uint32_t vh4[4], vl4[4];
                    ldm4t(vh4, Vh + voff);
                    ldm4t(vl4, Vl + voff);
                    mma16816(oa[n16 * 2],     ph, &vh4[0]);
                    mma16816(oa[n16 * 2 + 1], ph, &vh4[2]);
                    mma16816(oa[n16 * 2],     pl, &vh4[0]);
                    mma16816(oa[n16 * 2 + 1], pl, &vh4[2]);
                    mma16816(oa[n16 * 2],     ph, &vl4[0]);
                    mma16816(oa[n16 * 2 + 1], ph, &vl4[2]);
                }
            }
        }
        __syncthreads();
        a_load_kv(kvbase, buf, kt + 2, nkv, kvoff, tid);
    }

    // ---- epilogue: O/l -> fp32 g_att [m, H*HD] ----
    float inv0 = 1.0f / l0, inv1 = 1.0f / l1;
    const int r0 = q0 + wm + g;
    const int r1 = r0 + 8;
    size_t base0 = ((size_t)(b * S_) + r0) * NQ_ + h * HD_;
    size_t base1 = ((size_t)(b * S_) + r1) * NQ_ + h * HD_;
    #pragma unroll
    for (int nt = 0; nt < 16; nt++) {
        int c = nt * 8 + 2 * qd;
        *(float2*)&g_att[base0 + c] = make_float2(oa[nt][0] * inv0, oa[nt][1] * inv0);
        *(float2*)&g_att[base1 + c] = make_float2(oa[nt][2] * inv1, oa[nt][3] * inv1);
    }
}

// ---------------- launch ----------------
extern "C" void kernel_launch(void* const* d_in, const int* in_sizes, int n_in,
                              void* d_out, int out_size) {
    const float* x    = (const float*)d_in[0];
    const int*   wq   = (const int*)  d_in[1];
    const float* wqs  = (const float*)d_in[2];
    const int*   wk   = (const int*)  d_in[3];
    const float* wks  = (const float*)d_in[4];
    const int*   wv   = (const int*)  d_in[5];
    const float* wvs  = (const float*)d_in[6];
    const int*   wo   = (const int*)  d_in[7];
    const float* wos  = (const float*)d_in[8];
    const float* qnw  = (const float*)d_in[9];
    const float* knw  = (const float*)d_in[10];
    const float* cosc = (const float*)d_in[11];
    const float* sinc = (const float*)d_in[12];
    float* out = (float*)d_out;

    float *qp, *kp, *vp, *att, *xs, *as;
    int8_t *x8h, *x8l, *a8h, *a8l, *w8q, *w8k, *w8v, *w8o;
    cudaGetSymbolAddress((void**)&qp,  g_qproj);
    cudaGetSymbolAddress((void**)&kp,  g_kproj);
    cudaGetSymbolAddress((void**)&vp,  g_vproj);
    cudaGetSymbolAddress((void**)&att, g_att);
    cudaGetSymbolAddress((void**)&xs,  g_xs);
    cudaGetSymbolAddress((void**)&as,  g_as);
    cudaGetSymbolAddress((void**)&x8h, g_x8h);
    cudaGetSymbolAddress((void**)&x8l, g_x8l);
    cudaGetSymbolAddress((void**)&a8h, g_a8h);
    cudaGetSymbolAddress((void**)&a8l, g_a8l);
    cudaGetSymbolAddress((void**)&w8q, g_w8q);
    cudaGetSymbolAddress((void**)&w8k, g_w8k);
    cudaGetSymbolAddress((void**)&w8v, g_w8v);
    cudaGetSymbolAddress((void**)&w8o, g_w8o);

    // activation quantization + weight packing
    quant_rows<<<M_, 256>>>(x, x8h, x8l, xs);
    cvt_w8<<<(NQ_ * D_ / 4) / 256, 256>>>(wq, w8q);
    cvt_w8<<<(NKV_ * D_ / 4) / 256, 256>>>(wk, w8k);
    cvt_w8<<<(NKV_ * D_ / 4) / 256, 256>>>(wv, w8v);
    cvt_w8<<<(NQ_ * D_ / 4) / 256, 256>>>(wo, w8o);

    cudaFuncSetAttribute(gemm_i8, cudaFuncAttributeMaxDynamicSharedMemorySize, ISMEM_DYN);

    // QKV dequant projections (int8 IMMA)
    gemm_i8<<<dim3(NQ_ / 128,  M_ / 128), 256, ISMEM_DYN>>>(x8h, x8l, xs, w8q, wqs, qp, NQ_);
    gemm_i8<<<dim3(NKV_ / 128, M_ / 128), 256, ISMEM_DYN>>>(x8h, x8l, xs, w8k, wks, kp, NKV_);
    gemm_i8<<<dim3(NKV_ / 128, M_ / 128), 256, ISMEM_DYN>>>(x8h, x8l, xs, w8v, wvs, vp, NKV_);

    norm_rope<<<dim3(M_, H_ + 2 * KVH_), 128>>>(qnw, knw, cosc, sinc);

    cudaFuncSetAttribute(attn_mma, cudaFuncAttributeMaxDynamicSharedMemorySize, ASMEM);
    attn_mma<<<dim3(S_ / BQA, B_ * H_), 256, ASMEM>>>();

    // quantize attention output rows, then O projection (int8 IMMA)
    quant_rows<<<M_, 256>>>(att, a8h, a8l, as);
    gemm_i8<<<dim3(D_ / 128, M_ / 128), 256, ISMEM_DYN>>>(a8h, a8l, as, w8o, wos, out, D_);
}

// round 6
// speedup vs baseline: 2.1672x; 2.1672x over previous
#include <cuda_runtime.h>
#include <cuda_bf16.h>
#include <math.h>
#include <stdint.h>

#define B_   2
#define S_   2048
#define D_   2048
#define H_   16
#define KVH_ 8
#define HD_  128
#define M_   (B_ * S_)          // 4096
#define NQ_  (H_ * HD_)         // 2048
#define NKV_ (KVH_ * HD_)       // 1024
#define EPS_ 1e-6f

// ---------------- scratch (device globals, allocation-free) ----------------
__device__ __align__(256) __nv_bfloat16 g_xhi[M_ * D_];
__device__ __align__(256) __nv_bfloat16 g_xlo[M_ * D_];
__device__ __align__(256) __nv_bfloat16 g_ahi[M_ * NQ_];
__device__ __align__(256) __nv_bfloat16 g_alo[M_ * NQ_];
__device__ __align__(256) __nv_bfloat16 g_wqb[NQ_ * D_];
__device__ __align__(256) __nv_bfloat16 g_wkb[NKV_ * D_];
__device__ __align__(256) __nv_bfloat16 g_wvb[NKV_ * D_];
__device__ __align__(256) __nv_bfloat16 g_wob[D_ * NQ_];
__device__ __align__(256) __nv_bfloat16 g_Qhi[M_ * NQ_];
__device__ __align__(256) __nv_bfloat16 g_Qlo[M_ * NQ_];
__device__ __align__(256) __nv_bfloat16 g_Khi[M_ * NKV_];
__device__ __align__(256) __nv_bfloat16 g_Klo[M_ * NKV_];
__device__ __align__(256) __nv_bfloat16 g_Vhi[M_ * NKV_];
__device__ __align__(256) __nv_bfloat16 g_Vlo[M_ * NKV_];

// ---------------- PTX helpers (baseline PTX only) ----------------
__device__ __forceinline__ uint32_t smem_u32(const void* p) {
    uint32_t a;
    asm("{ .reg .u64 t; cvta.to.shared.u64 t, %1; cvt.u32.u64 %0, t; }" : "=r"(a) : "l"(p));
    return a;
}
__device__ __forceinline__ void cp16(uint32_t s, const void* g) {
    asm volatile("cp.async.cg.shared.global [%0], [%1], 16;" :: "r"(s), "l"(g));
}
#define CP_COMMIT() asm volatile("cp.async.commit_group;" ::: "memory")
#define CP_WAIT(n)  asm volatile("cp.async.wait_group %0;" :: "n"(n) : "memory")

__device__ __forceinline__ void ldm4(uint32_t* r, uint32_t addr) {
    asm volatile("ldmatrix.sync.aligned.m8n8.x4.shared.b16 {%0,%1,%2,%3}, [%4];"
                 : "=r"(r[0]), "=r"(r[1]), "=r"(r[2]), "=r"(r[3]) : "r"(addr));
}
__device__ __forceinline__ void ldm4t(uint32_t* r, uint32_t addr) {
    asm volatile("ldmatrix.sync.aligned.m8n8.x4.trans.shared.b16 {%0,%1,%2,%3}, [%4];"
                 : "=r"(r[0]), "=r"(r[1]), "=r"(r[2]), "=r"(r[3]) : "r"(addr));
}
__device__ __forceinline__ void mma16816(float* c, const uint32_t* a, const uint32_t* b) {
    asm volatile("mma.sync.aligned.m16n8k16.row.col.f32.bf16.bf16.f32 "
                 "{%0,%1,%2,%3}, {%4,%5,%6,%7}, {%8,%9}, {%0,%1,%2,%3};"
                 : "+f"(c[0]), "+f"(c[1]), "+f"(c[2]), "+f"(c[3])
                 : "r"(a[0]), "r"(a[1]), "r"(a[2]), "r"(a[3]), "r"(b[0]), "r"(b[1]));
}

__device__ __forceinline__ uint32_t sw128(uint32_t off) { return off ^ ((off >> 3) & 0x70); }
__device__ __forceinline__ uint32_t sw256(uint32_t off) { return off ^ ((off >> 4) & 0x70); }

__device__ __forceinline__ void split2(float a, float b, uint32_t& hi, uint32_t& lo) {
    __nv_bfloat162 h = __floats2bfloat162_rn(a, b);
    float ra = a - __bfloat162float(h.x);
    float rb = b - __bfloat162float(h.y);
    __nv_bfloat162 l = __floats2bfloat162_rn(ra, rb);
    hi = *(uint32_t*)&h;
    lo = *(uint32_t*)&l;
}

// ---------------- conversion kernels ----------------
__global__ void split_x_kernel(const float* __restrict__ x,
                               __nv_bfloat16* __restrict__ hi,
                               __nv_bfloat16* __restrict__ lo) {
    int i = blockIdx.x * blockDim.x + threadIdx.x;
    float4 v = ((const float4*)x)[i];
    __nv_bfloat16 h[4], l[4];
    float vv[4] = {v.x, v.y, v.z, v.w};
    #pragma unroll
    for (int j = 0; j < 4; j++) {
        h[j] = __float2bfloat16(vv[j]);
        l[j] = __float2bfloat16(vv[j] - __bfloat162float(h[j]));
    }
    ((uint2*)hi)[i] = *(uint2*)h;
    ((uint2*)lo)[i] = *(uint2*)l;
}

// all four weight arrays in one launch. unit = int4 (4 weights)
#define UQ (NQ_ * D_ / 4)
#define UK (NKV_ * D_ / 4)
__global__ void cvt_w_all(const int* __restrict__ wq, const int* __restrict__ wk,
                          const int* __restrict__ wv, const int* __restrict__ wo) {
    int i = blockIdx.x * blockDim.x + threadIdx.x;
    const int* src;
    __nv_bfloat16* dst;
    int k;
    if (i < UQ)                    { src = wq; dst = g_wqb; k = i; }
    else if (i < UQ + UK)          { src = wk; dst = g_wkb; k = i - UQ; }
    else if (i < UQ + 2 * UK)      { src = wv; dst = g_wvb; k = i - UQ - UK; }
    else                           { src = wo; dst = g_wob; k = i - UQ - 2 * UK; }
    int4 v = ((const int4*)src)[k];
    __nv_bfloat16 b[4];
    b[0] = __float2bfloat16((float)v.x);
    b[1] = __float2bfloat16((float)v.y);
    b[2] = __float2bfloat16((float)v.z);
    b[3] = __float2bfloat16((float)v.w);
    ((uint2*)dst)[k] = *(uint2*)b;
}

// ---------------- fused mma.sync bf16 GEMM + norm/rope/split epilogue -------
// C_full[m, c] = scale[n0+c] * sum_k (Ahi+Alo)[m,k] * W[n0+c,k], tile 128x128
// mode 0: RMSNorm(qnw)+RoPE -> g_Qhi/g_Qlo   [b,h,s,d], h = blockIdx.x, 16 heads
// mode 1: RMSNorm(knw)+RoPE -> g_Khi/g_Klo   8 heads
// mode 2: split             -> g_Vhi/g_Vlo   8 heads
// mode 3: fp32 store        -> C [m, N]
#define GBK       64
#define GCHUNK    (D_ / GBK)
#define GTILE_B   16384
#define GSTAGE_B  (3 * GTILE_B)
#define GSTG      3
#define GSMEM_DYN (GSTG * GSTAGE_B + 1024)

__device__ __forceinline__ void g_load_chunk(
    uint32_t tbase, int buf, int kc,
    const __nv_bfloat16* __restrict__ Ahi, const __nv_bfloat16* __restrict__ Alo,
    const __nv_bfloat16* __restrict__ W, int bm, int bn, int tid) {
    uint32_t st = tbase + buf * GSTAGE_B;
    const __nv_bfloat16* Ah = Ahi + (size_t)bm * D_ + kc * GBK;
    const __nv_bfloat16* Al = Alo + (size_t)bm * D_ + kc * GBK;
    const __nv_bfloat16* Wp = W   + (size_t)bn * D_ + kc * GBK;
    #pragma unroll
    for (int t = 0; t < 4; t++) {
        int idx = tid + t * 256;
        int row = idx >> 3;
        int seg = idx & 7;
        uint32_t off = sw128((uint32_t)(row * 128 + seg * 16));
        size_t gofs = (size_t)row * D_ + seg * 8;
        cp16(st + off,                 Ah + gofs);
        cp16(st + GTILE_B + off,       Al + gofs);
        cp16(st + 2 * GTILE_B + off,   Wp + gofs);
    }
    CP_COMMIT();
}

__global__ __launch_bounds__(256, 1)
void gemm_fused(const __nv_bfloat16* __restrict__ Ahi, const __nv_bfloat16* __restrict__ Alo,
                const __nv_bfloat16* __restrict__ W, const float* __restrict__ scale,
                int mode, const float* __restrict__ nw,
                const float* __restrict__ cosc, const float* __restrict__ sinc,
                float* __restrict__ C, int N,
                __nv_bfloat16* __restrict__ Dhi, __nv_bfloat16* __restrict__ Dlo) {
    extern __shared__ char dyns[];
    uint32_t tbase = (smem_u32(dyns) + 1023) & ~1023u;

    const int tid = threadIdx.x;
    const int wid = tid >> 5;
    const int L = tid & 31;
    const int bm = blockIdx.y * 128;
    const int bn = blockIdx.x * 128;        // also the head index * 128
    const int wm = wid * 16;                // warp: 16 rows x 128 cols

    g_load_chunk(tbase, 0, 0, Ahi, Alo, W, bm, bn, tid);
    g_load_chunk(tbase, 1, 1, Ahi, Alo, W, bm, bn, tid);

    float acc[16][4] = {};                  // [n8 tile j][frag]

    const int a_row = (L & 7) + ((L >> 3) & 1) * 8;
    const int a_kb  = (L >> 4) * 16;
    const int b_row = (L & 7) + ((L >> 4) << 3);
    const int b_kb  = ((L >> 3) & 1) * 16;

    int buf = 0;
    for (int kc = 0; kc < GCHUNK; kc++) {
        CP_WAIT(1);
        __syncthreads();
        if (kc + 2 < GCHUNK) {
            int nb = buf + 2; if (nb >= GSTG) nb -= GSTG;
            g_load_chunk(tbase, nb, kc + 2, Ahi, Alo, W, bm, bn, tid);
        } else {
            CP_COMMIT();
        }

        uint32_t st = tbase + buf * GSTAGE_B;
        #pragma unroll
        for (int ks = 0; ks < 4; ks++) {
            uint32_t ah[4], al[4], bb[8][4];
            uint32_t aoff = sw128((uint32_t)((wm + a_row) * 128 + ks * 32 + a_kb));
            ldm4(ah, st + aoff);
            ldm4(al, st + GTILE_B + aoff);
            #pragma unroll
            for (int nj = 0; nj < 8; nj++) {
                uint32_t off = sw128((uint32_t)((nj * 16 + b_row) * 128 + ks * 32 + b_kb));
                ldm4(bb[nj], st + 2 * GTILE_B + off);
            }
            #pragma unroll
            for (int j = 0; j < 16; j++) {
                const uint32_t* bf = &bb[j >> 1][(j & 1) * 2];
                mma16816(acc[j], ah, bf);
                mma16816(acc[j], al, bf);
            }
        }
        buf++; if (buf >= GSTG) buf = 0;
    }

    // ---------------- epilogue ----------------
    const int g = L >> 2;
    const int qd = L & 3;
    const int r0 = bm + wm + g;             // rows r0 and r0+8
    const int r1 = r0 + 8;

    // apply per-column scale; accumulate row sum of squares
    float ss0 = 0.0f, ss1 = 0.0f;
    #pragma unroll
    for (int j = 0; j < 16; j++) {
        int c = j * 8 + 2 * qd;
        float s0 = __ldg(&scale[bn + c]);
        float s1 = __ldg(&scale[bn + c + 1]);
        acc[j][0] *= s0; acc[j][1] *= s1;
        acc[j][2] *= s0; acc[j][3] *= s1;
        ss0 += acc[j][0] * acc[j][0] + acc[j][1] * acc[j][1];
        ss1 += acc[j][2] * acc[j][2] + acc[j][3] * acc[j][3];
    }

    if (mode == 3) {                        // O projection: fp32 store
        #pragma unroll
        for (int j = 0; j < 16; j++) {
            int c = bn + j * 8 + 2 * qd;
            *(float2*)&C[(size_t)r0 * N + c] = make_float2(acc[j][0], acc[j][1]);
            *(float2*)&C[(size_t)r1 * N + c] = make_float2(acc[j][2], acc[j][3]);
        }
        return;
    }

    const int b = r0 >> 11;                 // batch
    const int s0 = r0 & 2047;
    const int s1 = s0 + 8;
    const int h = bn >> 7;                  // head
    const int nheads = (mode == 0) ? H_ : KVH_;
    size_t base0 = ((size_t)(b * nheads + h) * S_ + s0) * HD_;
    size_t base1 = ((size_t)(b * nheads + h) * S_ + s1) * HD_;

    if (mode == 2) {                        // V: plain split
        #pragma unroll
        for (int j = 0; j < 16; j++) {
            int c = j * 8 + 2 * qd;
            uint32_t hi, lo;
            split2(acc[j][0], acc[j][1], hi, lo);
            *(uint32_t*)&Dhi[base0 + c] = hi;
            *(uint32_t*)&Dlo[base0 + c] = lo;
            split2(acc[j][2], acc[j][3], hi, lo);
            *(uint32_t*)&Dhi[base1 + c] = hi;
            *(uint32_t*)&Dlo[base1 + c] = lo;
        }
        return;
    }

    // Q/K: RMSNorm + RoPE
    ss0 += __shfl_xor_sync(0xffffffffu, ss0, 1);
    ss0 += __shfl_xor_sync(0xffffffffu, ss0, 2);
    ss1 += __shfl_xor_sync(0xffffffffu, ss1, 1);
    ss1 += __shfl_xor_sync(0xffffffffu, ss1, 2);
    float rms0 = rsqrtf(ss0 * (1.0f / HD_) + EPS_);
    float rms1 = rsqrtf(ss1 * (1.0f / HD_) + EPS_);

    #pragma unroll
    for (int j = 0; j < 8; j++) {
        int c = j * 8 + 2 * qd;             // c < 64, partner cp = c + 64
        int cp = c + 64;
        float w0a = __ldg(&nw[c]),  w0b = __ldg(&nw[c + 1]);
        float wpa = __ldg(&nw[cp]), wpb = __ldg(&nw[cp + 1]);
        // cos/sin: emb = concat(freqs,freqs) so cos(s,c) == cos(s,cp)
        float2 c0 = *(const float2*)&cosc[(size_t)s0 * HD_ + c];
        float2 n0 = *(const float2*)&sinc[(size_t)s0 * HD_ + c];
        float2 c1 = *(const float2*)&cosc[(size_t)s1 * HD_ + c];
        float2 n1 = *(const float2*)&sinc[(size_t)s1 * HD_ + c];

        // row r0
        float xa = acc[j][0] * rms0 * w0a,     xb = acc[j][1] * rms0 * w0b;
        float ya = acc[j + 8][0] * rms0 * wpa, yb = acc[j + 8][1] * rms0 * wpb;
        uint32_t hi, lo;
        split2(xa * c0.x - ya * n0.x, xb * c0.y - yb * n0.y, hi, lo);
        *(uint32_t*)&Dhi[base0 + c] = hi;  *(uint32_t*)&Dlo[base0 + c] = lo;
        split2(ya * c0.x + xa * n0.x, yb * c0.y + xb * n0.y, hi, lo);
        *(uint32_t*)&Dhi[base0 + cp] = hi; *(uint32_t*)&Dlo[base0 + cp] = lo;

        // row r1
        xa = acc[j][2] * rms1 * w0a;     xb = acc[j][3] * rms1 * w0b;
        ya = acc[j + 8][2] * rms1 * wpa; yb = acc[j + 8][3] * rms1 * wpb;
        split2(xa * c1.x - ya * n1.x, xb * c1.y - yb * n1.y, hi, lo);
        *(uint32_t*)&Dhi[base1 + c] = hi;  *(uint32_t*)&Dlo[base1 + c] = lo;
        split2(ya * c1.x + xa * n1.x, yb * c1.y + xb * n1.y, hi, lo);
        *(uint32_t*)&Dhi[base1 + cp] = hi; *(uint32_t*)&Dlo[base1 + cp] = lo;
    }
}

// ---------------- tensor-core flash attention (bf16 hi/lo, causal, GQA) -----
#define BQA 128
#define BKVA 64
#define AQ_BYTES   32768
#define AKV_STAGE  65536
#define ASMEM (2 * AQ_BYTES + 2 * AKV_STAGE)   // 192KB

__device__ __forceinline__ void a_load_kv(uint32_t kvbase, int buf, int kt, int nkv,
                                          size_t kvoff, int tid) {
    if (kt < nkv) {
        int k0 = kt * BKVA;
        uint32_t st = kvbase + buf * AKV_STAGE;
        #pragma unroll
        for (int t = 0; t < 4; t++) {
            int idx = tid + t * 256;
            int row = idx >> 4;
            int ch = idx & 15;
            uint32_t off = sw256((uint32_t)(row * 256 + ch * 16));
            size_t gi = kvoff + (size_t)(k0 + row) * HD_ + ch * 8;
            cp16(st + off,         g_Khi + gi);
            cp16(st + 16384 + off, g_Klo + gi);
            cp16(st + 32768 + off, g_Vhi + gi);
            cp16(st + 49152 + off, g_Vlo + gi);
        }
    }
    CP_COMMIT();
}

__global__ __launch_bounds__(256, 1)
void attn_mma() {
    extern __shared__ char smraw[];
    uint32_t sb = smem_u32(smraw);
    const int tid = threadIdx.x;
    const int wid = tid >> 5;
    const int L = tid & 31;
    const int g = L >> 2;
    const int qd = L & 3;

    const int qt = (int)gridDim.x - 1 - (int)blockIdx.x;
    const int bh = blockIdx.y;
    const int b = bh >> 4;
    const int h = bh & 15;
    const int kvh = h >> 1;
    const int q0 = qt * BQA;
    const int nkv = 2 * qt + 2;
    const int wm = wid * 16;

    const uint32_t Qh_s = sb;
    const uint32_t Ql_s = sb + AQ_BYTES;
    const uint32_t kvbase = sb + 2 * AQ_BYTES;

    const __nv_bfloat16* Qhg = g_Qhi + ((size_t)bh * S_ + q0) * HD_;
    const __nv_bfloat16* Qlg = g_Qlo + ((size_t)bh * S_ + q0) * HD_;
    const size_t kvoff = (size_t)(b * KVH_ + kvh) * S_ * HD_;

    #pragma unroll
    for (int t = 0; t < 8; t++) {
        int idx = tid + t * 256;
        int row = idx >> 4;
        int ch = idx & 15;
        uint32_t off = sw256((uint32_t)(row * 256 + ch * 16));
        size_t gi = (size_t)row * HD_ + ch * 8;
        cp16(Qh_s + off, Qhg + gi);
        cp16(Ql_s + off, Qlg + gi);
    }
    a_load_kv(kvbase, 0, 0, nkv, kvoff, tid);
    a_load_kv(kvbase, 1, 1, nkv, kvoff, tid);

    float m0 = -1e30f, m1 = -1e30f, l0 = 0.0f, l1 = 0.0f;
    float oa[16][4] = {};
    const float sc = 0.08838834764831845f;

    for (int kt = 0; kt < nkv; kt++) {
        CP_WAIT(1);
        __syncthreads();
        const int k0 = kt * BKVA;
        const int buf = kt & 1;
        if (k0 <= q0 + wm + 15) {
            uint32_t st = kvbase + buf * AKV_STAGE;
            uint32_t Kh = st, Kl = st + 16384, Vh = st + 32768, Vl = st + 49152;

            float sa[8][4] = {};
            const uint32_t a_part = (uint32_t)((L & 15) * 256 + ((L >> 4) << 4));
            const uint32_t b_row  = (uint32_t)((L & 7) + ((L >> 4) << 3));
            const uint32_t b_kb   = (uint32_t)(((L >> 3) & 1) * 16);
            #pragma unroll
            for (int k16 = 0; k16 < 8; k16++) {
                uint32_t qh[4], ql[4];
                uint32_t aoff = sw256((uint32_t)(wm * 256 + k16 * 32) + a_part);
                ldm4(qh, Qh_s + aoff);
                ldm4(ql, Ql_s + aoff);
                #pragma unroll
                for (int n16 = 0; n16 < 4; n16++) {
                    uint32_t boff = sw256((uint32_t)((n16 * 16 + b_row) * 256 + k16 * 32 + b_kb));
                    uint32_t kh4[4], kl4[4];
                    ldm4(kh4, Kh + boff);
                    ldm4(kl4, Kl + boff);
                    mma16816(sa[n16 * 2],     qh, &kh4[0]);
                    mma16816(sa[n16 * 2 + 1], qh, &kh4[2]);
                    mma16816(sa[n16 * 2],     ql, &kh4[0]);
                    mma16816(sa[n16 * 2 + 1], ql, &kh4[2]);
                    mma16816(sa[n16 * 2],     qh, &kl4[0]);
                    mma16816(sa[n16 * 2 + 1], qh, &kl4[2]);
                }
            }

            const int r0 = q0 + wm + g;
            const int r1 = r0 + 8;
            const bool needmask = (k0 + 63 > q0 + wm);
            #pragma unroll
            for (int t = 0; t < 8; t++) {
                #pragma unroll
                for (int c = 0; c < 4; c++) {
                    float v = sa[t][c] * sc;
                    if (needmask) {
                        int col = k0 + t * 8 + 2 * qd + (c & 1);
                        int row = (c < 2) ? r0 : r1;
                        if (col > row) v = -1e30f;
                    }
                    sa[t][c] = v;
                }
            }

            float mx0 = -1e30f, mx1 = -1e30f;
            #pragma unroll
            for (int t = 0; t < 8; t++) {
                mx0 = fmaxf(mx0, fmaxf(sa[t][0], sa[t][1]));
                mx1 = fmaxf(mx1, fmaxf(sa[t][2], sa[t][3]));
            }
            mx0 = fmaxf(mx0, __shfl_xor_sync(0xffffffffu, mx0, 1));
            mx0 = fmaxf(mx0, __shfl_xor_sync(0xffffffffu, mx0, 2));
            mx1 = fmaxf(mx1, __shfl_xor_sync(0xffffffffu, mx1, 1));
            mx1 = fmaxf(mx1, __shfl_xor_sync(0xffffffffu, mx1, 2));
            float nm0 = fmaxf(m0, mx0), nm1 = fmaxf(m1, mx1);
            float al0 = __expf(m0 - nm0), al1 = __expf(m1 - nm1);
            m0 = nm0; m1 = nm1;
            float rs0 = 0.0f, rs1 = 0.0f;
            #pragma unroll
            for (int t = 0; t < 8; t++) {
                float p0 = __expf(sa[t][0] - m0);
                float p1 = __expf(sa[t][1] - m0);
                float p2 = __expf(sa[t][2] - m1);
                float p3 = __expf(sa[t][3] - m1);
                sa[t][0] = p0; sa[t][1] = p1; sa[t][2] = p2; sa[t][3] = p3;
                rs0 += p0 + p1; rs1 += p2 + p3;
            }
            rs0 += __shfl_xor_sync(0xffffffffu, rs0, 1);
            rs0 += __shfl_xor_sync(0xffffffffu, rs0, 2);
            rs1 += __shfl_xor_sync(0xffffffffu, rs1, 1);
            rs1 += __shfl_xor_sync(0xffffffffu, rs1, 2);
            l0 = l0 * al0 + rs0;
            l1 = l1 * al1 + rs1;
            #pragma unroll
            for (int nt = 0; nt < 16; nt++) {
                oa[nt][0] *= al0; oa[nt][1] *= al0;
                oa[nt][2] *= al1; oa[nt][3] *= al1;
            }

            const uint32_t v_row = (uint32_t)((L & 7) + ((L >> 3) & 1) * 8);
            const uint32_t v_cb  = (uint32_t)((L >> 4) << 4);
            #pragma unroll
            for (int kk = 0; kk < 4; kk++) {
                const int t0 = 2 * kk, t1 = t0 + 1;
                uint32_t ph[4], pl[4];
                split2(sa[t0][0], sa[t0][1], ph[0], pl[0]);
                split2(sa[t0][2], sa[t0][3], ph[1], pl[1]);
                split2(sa[t1][0], sa[t1][1], ph[2], pl[2]);
                split2(sa[t1][2], sa[t1][3], ph[3], pl[3]);
                #pragma unroll
                for (int n16 = 0; n16 < 8; n16++) {
                    uint32_t voff = sw256((uint32_t)((kk * 16 + v_row) * 256 + n16 * 32) + v_cb);
                    uint32_t vh4[4], vl4[4];
                    ldm4t(vh4, Vh + voff);
                    ldm4t(vl4, Vl + voff);
                    mma16816(oa[n16 * 2],     ph, &vh4[0]);
                    mma16816(oa[n16 * 2 + 1], ph, &vh4[2]);
                    mma16816(oa[n16 * 2],     pl, &vh4[0]);
                    mma16816(oa[n16 * 2 + 1], pl, &vh4[2]);
                    mma16816(oa[n16 * 2],     ph, &vl4[0]);
                    mma16816(oa[n16 * 2 + 1], ph, &vl4[2]);
                }
            }
        }
        __syncthreads();
        a_load_kv(kvbase, buf, kt + 2, nkv, kvoff, tid);
    }

    // epilogue: O/l -> bf16 hi/lo in [m, H*HD]
    float inv0 = 1.0f / l0, inv1 = 1.0f / l1;
    const int r0 = q0 + wm + g;
    const int r1 = r0 + 8;
    size_t base0 = ((size_t)(b * S_) + r0) * NQ_ + h * HD_;
    size_t base1 = ((size_t)(b * S_) + r1) * NQ_ + h * HD_;
    #pragma unroll
    for (int nt = 0; nt < 16; nt++) {
        int c = nt * 8 + 2 * qd;
        uint32_t hi, lo;
        split2(oa[nt][0] * inv0, oa[nt][1] * inv0, hi, lo);
        *(uint32_t*)&g_ahi[base0 + c] = hi;
        *(uint32_t*)&g_alo[base0 + c] = lo;
        split2(oa[nt][2] * inv1, oa[nt][3] * inv1, hi, lo);
        *(uint32_t*)&g_ahi[base1 + c] = hi;
        *(uint32_t*)&g_alo[base1 + c] = lo;
    }
}

// ---------------- launch ----------------
extern "C" void kernel_launch(void* const* d_in, const int* in_sizes, int n_in,
                              void* d_out, int out_size) {
    const float* x    = (const float*)d_in[0];
    const int*   wq   = (const int*)  d_in[1];
    const float* wqs  = (const float*)d_in[2];
    const int*   wk   = (const int*)  d_in[3];
    const float* wks  = (const float*)d_in[4];
    const int*   wv   = (const int*)  d_in[5];
    const float* wvs  = (const float*)d_in[6];
    const int*   wo   = (const int*)  d_in[7];
    const float* wos  = (const float*)d_in[8];
    const float* qnw  = (const float*)d_in[9];
    const float* knw  = (const float*)d_in[10];
    const float* cosc = (const float*)d_in[11];
    const float* sinc = (const float*)d_in[12];
    float* out = (float*)d_out;

    __nv_bfloat16 *xhi, *xlo, *ahi, *alo, *wqb, *wkb, *wvb, *wob;
    __nv_bfloat16 *Qhi, *Qlo, *Khi, *Klo, *Vhi, *Vlo;
    cudaGetSymbolAddress((void**)&xhi, g_xhi);
    cudaGetSymbolAddress((void**)&xlo, g_xlo);
    cudaGetSymbolAddress((void**)&ahi, g_ahi);
    cudaGetSymbolAddress((void**)&alo, g_alo);
    cudaGetSymbolAddress((void**)&wqb, g_wqb);
    cudaGetSymbolAddress((void**)&wkb, g_wkb);
    cudaGetSymbolAddress((void**)&wvb, g_wvb);
    cudaGetSymbolAddress((void**)&wob, g_wob);
    cudaGetSymbolAddress((void**)&Qhi, g_Qhi);
    cudaGetSymbolAddress((void**)&Qlo, g_Qlo);
    cudaGetSymbolAddress((void**)&Khi, g_Khi);
    cudaGetSymbolAddress((void**)&Klo, g_Klo);
    cudaGetSymbolAddress((void**)&Vhi, g_Vhi);
    cudaGetSymbolAddress((void**)&Vlo, g_Vlo);

    split_x_kernel<<<(M_ * D_ / 4) / 256, 256>>>(x, xhi, xlo);
    cvt_w_all<<<(2 * UQ + 2 * UK) / 256, 256>>>(wq, wk, wv, wo);

    cudaFuncSetAttribute(gemm_fused, cudaFuncAttributeMaxDynamicSharedMemorySize, GSMEM_DYN);

    // fused projections: GEMM + norm + rope + bf16 split, straight to Q/K/V
    gemm_fused<<<dim3(NQ_ / 128,  M_ / 128), 256, GSMEM_DYN>>>(
        xhi, xlo, wqb, wqs, 0, qnw, cosc, sinc, nullptr, 0, Qhi, Qlo);
    gemm_fused<<<dim3(NKV_ / 128, M_ / 128), 256, GSMEM_DYN>>>(
        xhi, xlo, wkb, wks, 1, knw, cosc, sinc, nullptr, 0, Khi, Klo);
    gemm_fused<<<dim3(NKV_ / 128, M_ / 128), 256, GSMEM_DYN>>>(
        xhi, xlo, wvb, wvs, 2, nullptr, nullptr, nullptr, nullptr, 0, Vhi, Vlo);

    cudaFuncSetAttribute(attn_mma, cudaFuncAttributeMaxDynamicSharedMemorySize, ASMEM);
    attn_mma<<<dim3(S_ / BQA, B_ * H_), 256, ASMEM>>>();

    // O projection straight into d_out
    gemm_fused<<<dim3(D_ / 128, M_ / 128), 256, GSMEM_DYN>>>(
        ahi, alo, wob, wos, 3, nullptr, nullptr, nullptr, out, D_, nullptr, nullptr);
}

// round 7
// speedup vs baseline: 3.5975x; 1.6600x over previous
#include <cuda_runtime.h>
#include <cuda_fp16.h>
#include <math.h>
#include <stdint.h>

#define B_   2
#define S_   2048
#define D_   2048
#define H_   16
#define KVH_ 8
#define HD_  128
#define M_   (B_ * S_)          // 4096
#define NQ_  (H_ * HD_)         // 2048
#define NKV_ (KVH_ * HD_)       // 1024
#define EPS_ 1e-6f

// ---------------- scratch (device globals, allocation-free) ----------------
__device__ __align__(256) __half g_x16[M_ * D_];
__device__ __align__(256) __half g_a16[M_ * NQ_];
__device__ __align__(256) __half g_wq16[NQ_ * D_];
__device__ __align__(256) __half g_wk16[NKV_ * D_];
__device__ __align__(256) __half g_wv16[NKV_ * D_];
__device__ __align__(256) __half g_wo16[D_ * NQ_];
__device__ __align__(256) __half g_Q16[M_ * NQ_];
__device__ __align__(256) __half g_K16[M_ * NKV_];
__device__ __align__(256) __half g_V16[M_ * NKV_];

// ---------------- PTX helpers (baseline PTX only) ----------------
__device__ __forceinline__ uint32_t smem_u32(const void* p) {
    uint32_t a;
    asm("{ .reg .u64 t; cvta.to.shared.u64 t, %1; cvt.u32.u64 %0, t; }" : "=r"(a) : "l"(p));
    return a;
}
__device__ __forceinline__ void cp16(uint32_t s, const void* g) {
    asm volatile("cp.async.cg.shared.global [%0], [%1], 16;" :: "r"(s), "l"(g));
}
#define CP_COMMIT() asm volatile("cp.async.commit_group;" ::: "memory")
#define CP_WAIT(n)  asm volatile("cp.async.wait_group %0;" :: "n"(n) : "memory")

__device__ __forceinline__ void ldm4(uint32_t* r, uint32_t addr) {
    asm volatile("ldmatrix.sync.aligned.m8n8.x4.shared.b16 {%0,%1,%2,%3}, [%4];"
                 : "=r"(r[0]), "=r"(r[1]), "=r"(r[2]), "=r"(r[3]) : "r"(addr));
}
__device__ __forceinline__ void ldm4t(uint32_t* r, uint32_t addr) {
    asm volatile("ldmatrix.sync.aligned.m8n8.x4.trans.shared.b16 {%0,%1,%2,%3}, [%4];"
                 : "=r"(r[0]), "=r"(r[1]), "=r"(r[2]), "=r"(r[3]) : "r"(addr));
}
__device__ __forceinline__ void mma16816(float* c, const uint32_t* a, const uint32_t* b) {
    asm volatile("mma.sync.aligned.m16n8k16.row.col.f32.f16.f16.f32 "
                 "{%0,%1,%2,%3}, {%4,%5,%6,%7}, {%8,%9}, {%0,%1,%2,%3};"
                 : "+f"(c[0]), "+f"(c[1]), "+f"(c[2]), "+f"(c[3])
                 : "r"(a[0]), "r"(a[1]), "r"(a[2]), "r"(a[3]), "r"(b[0]), "r"(b[1]));
}

__device__ __forceinline__ uint32_t sw128(uint32_t off) { return off ^ ((off >> 3) & 0x70); }
__device__ __forceinline__ uint32_t sw256(uint32_t off) { return off ^ ((off >> 4) & 0x70); }

__device__ __forceinline__ uint32_t packh2(float a, float b) {
    __half2 h = __floats2half2_rn(a, b);
    return *(uint32_t*)&h;
}

// ---------------- conversion kernels ----------------
__global__ void cvt_x_kernel(const float* __restrict__ x, __half* __restrict__ o) {
    int i = blockIdx.x * blockDim.x + threadIdx.x;   // one float4
    float4 v = ((const float4*)x)[i];
    uint2 p;
    p.x = packh2(v.x, v.y);
    p.y = packh2(v.z, v.w);
    ((uint2*)o)[i] = p;
}

#define UQ (NQ_ * D_ / 4)
#define UK (NKV_ * D_ / 4)
__global__ void cvt_w_all(const int* __restrict__ wq, const int* __restrict__ wk,
                          const int* __restrict__ wv, const int* __restrict__ wo) {
    int i = blockIdx.x * blockDim.x + threadIdx.x;
    const int* src;
    __half* dst;
    int k;
    if (i < UQ)                    { src = wq; dst = g_wq16; k = i; }
    else if (i < UQ + UK)          { src = wk; dst = g_wk16; k = i - UQ; }
    else if (i < UQ + 2 * UK)      { src = wv; dst = g_wv16; k = i - UQ - UK; }
    else                           { src = wo; dst = g_wo16; k = i - UQ - 2 * UK; }
    int4 v = ((const int4*)src)[k];
    uint2 p;
    p.x = packh2((float)v.x, (float)v.y);
    p.y = packh2((float)v.z, (float)v.w);
    ((uint2*)dst)[k] = p;
}

// ---------------- fused fp16 mma GEMM + norm/rope epilogue ----------------
// C_full[m, c] = scale[n0+c] * sum_k A[m,k] * W[n0+c,k], tile 128x128
// mode 0: RMSNorm(qnw)+RoPE -> g_Q16 ; mode 1: -> g_K16 ; mode 2: cvt -> g_V16
// mode 3: fp32 store -> C [m, N]
#define GBK       64
#define GCHUNK    (D_ / GBK)
#define GTILE_B   16384
#define GSTAGE_B  (2 * GTILE_B)
#define GSTG      3
#define GSMEM_DYN (GSTG * GSTAGE_B + 1024)

__device__ __forceinline__ void g_load_chunk(
    uint32_t tbase, int buf, int kc,
    const __half* __restrict__ A, const __half* __restrict__ W,
    int bm, int bn, int tid) {
    uint32_t st = tbase + buf * GSTAGE_B;
    const __half* Ap = A + (size_t)bm * D_ + kc * GBK;
    const __half* Wp = W + (size_t)bn * D_ + kc * GBK;
    #pragma unroll
    for (int t = 0; t < 4; t++) {
        int idx = tid + t * 256;
        int row = idx >> 3;
        int seg = idx & 7;
        uint32_t off = sw128((uint32_t)(row * 128 + seg * 16));
        size_t gofs = (size_t)row * D_ + seg * 8;
        cp16(st + off,           Ap + gofs);
        cp16(st + GTILE_B + off, Wp + gofs);
    }
    CP_COMMIT();
}

__global__ __launch_bounds__(256, 1)
void gemm_fused(const __half* __restrict__ A, const __half* __restrict__ W,
                const float* __restrict__ scale,
                int mode, const float* __restrict__ nw,
                const float* __restrict__ cosc, const float* __restrict__ sinc,
                float* __restrict__ C, int N, __half* __restrict__ Dst) {
    extern __shared__ char dyns[];
    uint32_t tbase = (smem_u32(dyns) + 1023) & ~1023u;

    const int tid = threadIdx.x;
    const int wid = tid >> 5;
    const int L = tid & 31;
    const int bm = blockIdx.y * 128;
    const int bn = blockIdx.x * 128;        // head * 128 for modes 0-2
    const int wm = wid * 16;                // warp: 16 rows x 128 cols

    g_load_chunk(tbase, 0, 0, A, W, bm, bn, tid);
    g_load_chunk(tbase, 1, 1, A, W, bm, bn, tid);

    float acc[16][4] = {};

    const int a_row = (L & 7) + ((L >> 3) & 1) * 8;
    const int a_kb  = (L >> 4) * 16;
    const int b_row = (L & 7) + ((L >> 4) << 3);
    const int b_kb  = ((L >> 3) & 1) * 16;

    int buf = 0;
    for (int kc = 0; kc < GCHUNK; kc++) {
        CP_WAIT(1);
        __syncthreads();
        if (kc + 2 < GCHUNK) {
            int nb = buf + 2; if (nb >= GSTG) nb -= GSTG;
            g_load_chunk(tbase, nb, kc + 2, A, W, bm, bn, tid);
        } else {
            CP_COMMIT();
        }

        uint32_t st = tbase + buf * GSTAGE_B;
        #pragma unroll
        for (int ks = 0; ks < 4; ks++) {
            uint32_t ah[4], bb[8][4];
            uint32_t aoff = sw128((uint32_t)((wm + a_row) * 128 + ks * 32 + a_kb));
            ldm4(ah, st + aoff);
            #pragma unroll
            for (int nj = 0; nj < 8; nj++) {
                uint32_t off = sw128((uint32_t)((nj * 16 + b_row) * 128 + ks * 32 + b_kb));
                ldm4(bb[nj], st + GTILE_B + off);
            }
            #pragma unroll
            for (int j = 0; j < 16; j++) {
                const uint32_t* bf = &bb[j >> 1][(j & 1) * 2];
                mma16816(acc[j], ah, bf);
            }
        }
        buf++; if (buf >= GSTG) buf = 0;
    }

    // ---------------- epilogue ----------------
    const int g = L >> 2;
    const int qd = L & 3;
    const int r0 = bm + wm + g;
    const int r1 = r0 + 8;

    float ss0 = 0.0f, ss1 = 0.0f;
    #pragma unroll
    for (int j = 0; j < 16; j++) {
        int c = j * 8 + 2 * qd;
        float s0 = __ldg(&scale[bn + c]);
        float s1 = __ldg(&scale[bn + c + 1]);
        acc[j][0] *= s0; acc[j][1] *= s1;
        acc[j][2] *= s0; acc[j][3] *= s1;
        ss0 += acc[j][0] * acc[j][0] + acc[j][1] * acc[j][1];
        ss1 += acc[j][2] * acc[j][2] + acc[j][3] * acc[j][3];
    }

    if (mode == 3) {
        #pragma unroll
        for (int j = 0; j < 16; j++) {
            int c = bn + j * 8 + 2 * qd;
            *(float2*)&C[(size_t)r0 * N + c] = make_float2(acc[j][0], acc[j][1]);
            *(float2*)&C[(size_t)r1 * N + c] = make_float2(acc[j][2], acc[j][3]);
        }
        return;
    }

    const int b = r0 >> 11;
    const int s0 = r0 & 2047;
    const int s1 = s0 + 8;
    const int h = bn >> 7;
    const int nheads = (mode == 0) ? H_ : KVH_;
    size_t base0 = ((size_t)(b * nheads + h) * S_ + s0) * HD_;
    size_t base1 = ((size_t)(b * nheads + h) * S_ + s1) * HD_;

    if (mode == 2) {                        // V: plain fp16 convert
        #pragma unroll
        for (int j = 0; j < 16; j++) {
            int c = j * 8 + 2 * qd;
            *(uint32_t*)&Dst[base0 + c] = packh2(acc[j][0], acc[j][1]);
            *(uint32_t*)&Dst[base1 + c] = packh2(acc[j][2], acc[j][3]);
        }
        return;
    }

    // Q/K: RMSNorm + RoPE
    ss0 += __shfl_xor_sync(0xffffffffu, ss0, 1);
    ss0 += __shfl_xor_sync(0xffffffffu, ss0, 2);
    ss1 += __shfl_xor_sync(0xffffffffu, ss1, 1);
    ss1 += __shfl_xor_sync(0xffffffffu, ss1, 2);
    float rms0 = rsqrtf(ss0 * (1.0f / HD_) + EPS_);
    float rms1 = rsqrtf(ss1 * (1.0f / HD_) + EPS_);

    #pragma unroll
    for (int j = 0; j < 8; j++) {
        int c = j * 8 + 2 * qd;
        int cp = c + 64;
        float w0a = __ldg(&nw[c]),  w0b = __ldg(&nw[c + 1]);
        float wpa = __ldg(&nw[cp]), wpb = __ldg(&nw[cp + 1]);
        float2 c0 = *(const float2*)&cosc[(size_t)s0 * HD_ + c];
        float2 n0 = *(const float2*)&sinc[(size_t)s0 * HD_ + c];
        float2 c1 = *(const float2*)&cosc[(size_t)s1 * HD_ + c];
        float2 n1 = *(const float2*)&sinc[(size_t)s1 * HD_ + c];

        float xa = acc[j][0] * rms0 * w0a,     xb = acc[j][1] * rms0 * w0b;
        float ya = acc[j + 8][0] * rms0 * wpa, yb = acc[j + 8][1] * rms0 * wpb;
        *(uint32_t*)&Dst[base0 + c]  = packh2(xa * c0.x - ya * n0.x, xb * c0.y - yb * n0.y);
        *(uint32_t*)&Dst[base0 + cp] = packh2(ya * c0.x + xa * n0.x, yb * c0.y + xb * n0.y);

        xa = acc[j][2] * rms1 * w0a;     xb = acc[j][3] * rms1 * w0b;
        ya = acc[j + 8][2] * rms1 * wpa; yb = acc[j + 8][3] * rms1 * wpb;
        *(uint32_t*)&Dst[base1 + c]  = packh2(xa * c1.x - ya * n1.x, xb * c1.y - yb * n1.y);
        *(uint32_t*)&Dst[base1 + cp] = packh2(ya * c1.x + xa * n1.x, yb * c1.y + xb * n1.y);
    }
}

// ---------------- fp16 tensor-core flash attention (causal, GQA) -----------
#define BQA 128
#define BKVA 64
#define AQ_BYTES   32768        // 128 rows x 256B
#define AKV_STAGE  32768        // K 16KB + V 16KB
#define ASMEM (AQ_BYTES + 2 * AKV_STAGE)   // 96KB

__device__ __forceinline__ void a_load_kv(uint32_t kvbase, int buf, int kt, int nkv,
                                          size_t kvoff, int tid) {
    if (kt < nkv) {
        int k0 = kt * BKVA;
        uint32_t st = kvbase + buf * AKV_STAGE;
        #pragma unroll
        for (int t = 0; t < 4; t++) {
            int idx = tid + t * 256;
            int row = idx >> 4;
            int ch = idx & 15;
            uint32_t off = sw256((uint32_t)(row * 256 + ch * 16));
            size_t gi = kvoff + (size_t)(k0 + row) * HD_ + ch * 8;
            cp16(st + off,         g_K16 + gi);
            cp16(st + 16384 + off, g_V16 + gi);
        }
    }
    CP_COMMIT();
}

__global__ __launch_bounds__(256, 1)
void attn_mma() {
    extern __shared__ char smraw[];
    uint32_t sb = smem_u32(smraw);
    const int tid = threadIdx.x;
    const int wid = tid >> 5;
    const int L = tid & 31;
    const int g = L >> 2;
    const int qd = L & 3;

    const int qt = (int)gridDim.x - 1 - (int)blockIdx.x;
    const int bh = blockIdx.y;
    const int b = bh >> 4;
    const int h = bh & 15;
    const int kvh = h >> 1;
    const int q0 = qt * BQA;
    const int nkv = 2 * qt + 2;
    const int wm = wid * 16;

    const uint32_t Q_s = sb;
    const uint32_t kvbase = sb + AQ_BYTES;

    const __half* Qg = g_Q16 + ((size_t)bh * S_ + q0) * HD_;
    const size_t kvoff = (size_t)(b * KVH_ + kvh) * S_ * HD_;

    #pragma unroll
    for (int t = 0; t < 8; t++) {
        int idx = tid + t * 256;
        int row = idx >> 4;
        int ch = idx & 15;
        uint32_t off = sw256((uint32_t)(row * 256 + ch * 16));
        cp16(Q_s + off, Qg + (size_t)row * HD_ + ch * 8);
    }
    a_load_kv(kvbase, 0, 0, nkv, kvoff, tid);
    a_load_kv(kvbase, 1, 1, nkv, kvoff, tid);

    float m0 = -1e30f, m1 = -1e30f, l0 = 0.0f, l1 = 0.0f;
    float oa[16][4] = {};
    const float sc = 0.08838834764831845f;

    for (int kt = 0; kt < nkv; kt++) {
        CP_WAIT(1);
        __syncthreads();
        const int k0 = kt * BKVA;
        const int buf = kt & 1;
        if (k0 <= q0 + wm + 15) {
            uint32_t st = kvbase + buf * AKV_STAGE;
            uint32_t Kh = st, Vh = st + 16384;

            float sa[8][4] = {};
            const uint32_t a_part = (uint32_t)((L & 15) * 256 + ((L >> 4) << 4));
            const uint32_t b_row  = (uint32_t)((L & 7) + ((L >> 4) << 3));
            const uint32_t b_kb   = (uint32_t)(((L >> 3) & 1) * 16);
            #pragma unroll
            for (int k16 = 0; k16 < 8; k16++) {
                uint32_t qh[4];
                uint32_t aoff = sw256((uint32_t)(wm * 256 + k16 * 32) + a_part);
                ldm4(qh, Q_s + aoff);
                #pragma unroll
                for (int n16 = 0; n16 < 4; n16++) {
                    uint32_t boff = sw256((uint32_t)((n16 * 16 + b_row) * 256 + k16 * 32 + b_kb));
                    uint32_t kh4[4];
                    ldm4(kh4, Kh + boff);
                    mma16816(sa[n16 * 2],     qh, &kh4[0]);
                    mma16816(sa[n16 * 2 + 1], qh, &kh4[2]);
                }
            }

            const int r0 = q0 + wm + g;
            const int r1 = r0 + 8;
            const bool needmask = (k0 + 63 > q0 + wm);
            #pragma unroll
            for (int t = 0; t < 8; t++) {
                #pragma unroll
                for (int c = 0; c < 4; c++) {
                    float v = sa[t][c] * sc;
                    if (needmask) {
                        int col = k0 + t * 8 + 2 * qd + (c & 1);
                        int row = (c < 2) ? r0 : r1;
                        if (col > row) v = -1e30f;
                    }
                    sa[t][c] = v;
                }
            }

            float mx0 = -1e30f, mx1 = -1e30f;
            #pragma unroll
            for (int t = 0; t < 8; t++) {
                mx0 = fmaxf(mx0, fmaxf(sa[t][0], sa[t][1]));
                mx1 = fmaxf(mx1, fmaxf(sa[t][2], sa[t][3]));
            }
            mx0 = fmaxf(mx0, __shfl_xor_sync(0xffffffffu, mx0, 1));
            mx0 = fmaxf(mx0, __shfl_xor_sync(0xffffffffu, mx0, 2));
            mx1 = fmaxf(mx1, __shfl_xor_sync(0xffffffffu, mx1, 1));
            mx1 = fmaxf(mx1, __shfl_xor_sync(0xffffffffu, mx1, 2));
            float nm0 = fmaxf(m0, mx0), nm1 = fmaxf(m1, mx1);
            float al0 = __expf(m0 - nm0), al1 = __expf(m1 - nm1);
            m0 = nm0; m1 = nm1;
            float rs0 = 0.0f, rs1 = 0.0f;
            #pragma unroll
            for (int t = 0; t < 8; t++) {
                float p0 = __expf(sa[t][0] - m0);
                float p1 = __expf(sa[t][1] - m0);
                float p2 = __expf(sa[t][2] - m1);
                float p3 = __expf(sa[t][3] - m1);
                sa[t][0] = p0; sa[t][1] = p1; sa[t][2] = p2; sa[t][3] = p3;
                rs0 += p0 + p1; rs1 += p2 + p3;
            }
            rs0 += __shfl_xor_sync(0xffffffffu, rs0, 1);
            rs0 += __shfl_xor_sync(0xffffffffu, rs0, 2);
            rs1 += __shfl_xor_sync(0xffffffffu, rs1, 1);
            rs1 += __shfl_xor_sync(0xffffffffu, rs1, 2);
            l0 = l0 * al0 + rs0;
            l1 = l1 * al1 + rs1;
            #pragma unroll
            for (int nt = 0; nt < 16; nt++) {
                oa[nt][0] *= al0; oa[nt][1] *= al0;
                oa[nt][2] *= al1; oa[nt][3] *= al1;
            }

            const uint32_t v_row = (uint32_t)((L & 7) + ((L >> 3) & 1) * 8);
            const uint32_t v_cb  = (uint32_t)((L >> 4) << 4);
            #pragma unroll
            for (int kk = 0; kk < 4; kk++) {
                const int t0 = 2 * kk, t1 = t0 + 1;
                uint32_t ph[4];
                ph[0] = packh2(sa[t0][0], sa[t0][1]);
                ph[1] = packh2(sa[t0][2], sa[t0][3]);
                ph[2] = packh2(sa[t1][0], sa[t1][1]);
                ph[3] = packh2(sa[t1][2], sa[t1][3]);
                #pragma unroll
                for (int n16 = 0; n16 < 8; n16++) {
                    uint32_t voff = sw256((uint32_t)((kk * 16 + v_row) * 256 + n16 * 32) + v_cb);
                    uint32_t vh4[4];
                    ldm4t(vh4, Vh + voff);
                    mma16816(oa[n16 * 2],     ph, &vh4[0]);
                    mma16816(oa[n16 * 2 + 1], ph, &vh4[2]);
                }
            }
        }
        __syncthreads();
        a_load_kv(kvbase, buf, kt + 2, nkv, kvoff, tid);
    }

    // epilogue: O/l -> fp16 in [m, H*HD]
    float inv0 = 1.0f / l0, inv1 = 1.0f / l1;
    const int r0 = q0 + wm + g;
    const int r1 = r0 + 8;
    size_t base0 = ((size_t)(b * S_) + r0) * NQ_ + h * HD_;
    size_t base1 = ((size_t)(b * S_) + r1) * NQ_ + h * HD_;
    #pragma unroll
    for (int nt = 0; nt < 16; nt++) {
        int c = nt * 8 + 2 * qd;
        *(uint32_t*)&g_a16[base0 + c] = packh2(oa[nt][0] * inv0, oa[nt][1] * inv0);
        *(uint32_t*)&g_a16[base1 + c] = packh2(oa[nt][2] * inv1, oa[nt][3] * inv1);
    }
}

// ---------------- launch ----------------
extern "C" void kernel_launch(void* const* d_in, const int* in_sizes, int n_in,
                              void* d_out, int out_size) {
    const float* x    = (const float*)d_in[0];
    const int*   wq   = (const int*)  d_in[1];
    const float* wqs  = (const float*)d_in[2];
    const int*   wk   = (const int*)  d_in[3];
    const float* wks  = (const float*)d_in[4];
    const int*   wv   = (const int*)  d_in[5];
    const float* wvs  = (const float*)d_in[6];
    const int*   wo   = (const int*)  d_in[7];
    const float* wos  = (const float*)d_in[8];
    const float* qnw  = (const float*)d_in[9];
    const float* knw  = (const float*)d_in[10];
    const float* cosc = (const float*)d_in[11];
    const float* sinc = (const float*)d_in[12];
    float* out = (float*)d_out;

    __half *x16, *a16, *wq16, *wk16, *wv16, *wo16, *Q16, *K16, *V16;
    cudaGetSymbolAddress((void**)&x16,  g_x16);
    cudaGetSymbolAddress((void**)&a16,  g_a16);
    cudaGetSymbolAddress((void**)&wq16, g_wq16);
    cudaGetSymbolAddress((void**)&wk16, g_wk16);
    cudaGetSymbolAddress((void**)&wv16, g_wv16);
    cudaGetSymbolAddress((void**)&wo16, g_wo16);
    cudaGetSymbolAddress((void**)&Q16,  g_Q16);
    cudaGetSymbolAddress((void**)&K16,  g_K16);
    cudaGetSymbolAddress((void**)&V16,  g_V16);

    cvt_x_kernel<<<(M_ * D_ / 4) / 256, 256>>>(x, x16);
    cvt_w_all<<<(2 * UQ + 2 * UK) / 256, 256>>>(wq, wk, wv, wo);

    cudaFuncSetAttribute(gemm_fused, cudaFuncAttributeMaxDynamicSharedMemorySize, GSMEM_DYN);

    gemm_fused<<<dim3(NQ_ / 128,  M_ / 128), 256, GSMEM_DYN>>>(
        x16, wq16, wqs, 0, qnw, cosc, sinc, nullptr, 0, Q16);
    gemm_fused<<<dim3(NKV_ / 128, M_ / 128), 256, GSMEM_DYN>>>(
        x16, wk16, wks, 1, knw, cosc, sinc, nullptr, 0, K16);
    gemm_fused<<<dim3(NKV_ / 128, M_ / 128), 256, GSMEM_DYN>>>(
        x16, wv16, wvs, 2, nullptr, nullptr, nullptr, nullptr, 0, V16);

    cudaFuncSetAttribute(attn_mma, cudaFuncAttributeMaxDynamicSharedMemorySize, ASMEM);
    attn_mma<<<dim3(S_ / BQA, B_ * H_), 256, ASMEM>>>();

    gemm_fused<<<dim3(D_ / 128, M_ / 128), 256, GSMEM_DYN>>>(
        a16, wo16, wos, 3, nullptr, nullptr, nullptr, out, D_, nullptr);
}

// round 8
// speedup vs baseline: 3.9984x; 1.1114x over previous
#include <cuda_runtime.h>
#include <cuda_fp16.h>
#include <math.h>
#include <stdint.h>

#define B_   2
#define S_   2048
#define D_   2048
#define H_   16
#define KVH_ 8
#define HD_  128
#define M_   (B_ * S_)          // 4096
#define NQ_  (H_ * HD_)         // 2048
#define NKV_ (KVH_ * HD_)       // 1024
#define EPS_ 1e-6f

// ---------------- scratch (device globals, allocation-free) ----------------
__device__ __align__(256) __half g_x16[M_ * D_];
__device__ __align__(256) __half g_a16[M_ * NQ_];
__device__ __align__(256) __half g_wq16[NQ_ * D_];
__device__ __align__(256) __half g_wk16[NKV_ * D_];
__device__ __align__(256) __half g_wv16[NKV_ * D_];
__device__ __align__(256) __half g_wo16[D_ * NQ_];
__device__ __align__(256) __half g_Q16[M_ * NQ_];
__device__ __align__(256) __half g_K16[M_ * NKV_];
__device__ __align__(256) __half g_V16[M_ * NKV_];

// ---------------- PTX helpers (baseline PTX only) ----------------
__device__ __forceinline__ uint32_t smem_u32(const void* p) {
    uint32_t a;
    asm("{ .reg .u64 t; cvta.to.shared.u64 t, %1; cvt.u32.u64 %0, t; }" : "=r"(a) : "l"(p));
    return a;
}
__device__ __forceinline__ void cp16(uint32_t s, const void* g) {
    asm volatile("cp.async.cg.shared.global [%0], [%1], 16;" :: "r"(s), "l"(g));
}
#define CP_COMMIT() asm volatile("cp.async.commit_group;" ::: "memory")
#define CP_WAIT(n)  asm volatile("cp.async.wait_group %0;" :: "n"(n) : "memory")

__device__ __forceinline__ void ldm4(uint32_t* r, uint32_t addr) {
    asm volatile("ldmatrix.sync.aligned.m8n8.x4.shared.b16 {%0,%1,%2,%3}, [%4];"
                 : "=r"(r[0]), "=r"(r[1]), "=r"(r[2]), "=r"(r[3]) : "r"(addr));
}
__device__ __forceinline__ void ldm4t(uint32_t* r, uint32_t addr) {
    asm volatile("ldmatrix.sync.aligned.m8n8.x4.trans.shared.b16 {%0,%1,%2,%3}, [%4];"
                 : "=r"(r[0]), "=r"(r[1]), "=r"(r[2]), "=r"(r[3]) : "r"(addr));
}
__device__ __forceinline__ void mma16816(float* c, const uint32_t* a, const uint32_t* b) {
    asm volatile("mma.sync.aligned.m16n8k16.row.col.f32.f16.f16.f32 "
                 "{%0,%1,%2,%3}, {%4,%5,%6,%7}, {%8,%9}, {%0,%1,%2,%3};"
                 : "+f"(c[0]), "+f"(c[1]), "+f"(c[2]), "+f"(c[3])
                 : "r"(a[0]), "r"(a[1]), "r"(a[2]), "r"(a[3]), "r"(b[0]), "r"(b[1]));
}

__device__ __forceinline__ uint32_t sw128(uint32_t off) { return off ^ ((off >> 3) & 0x70); }
__device__ __forceinline__ uint32_t sw256(uint32_t off) { return off ^ ((off >> 4) & 0x70); }

__device__ __forceinline__ uint32_t packh2(float a, float b) {
    __half2 h = __floats2half2_rn(a, b);
    return *(uint32_t*)&h;
}

// ---------------- conversion kernels ----------------
__global__ void cvt_x_kernel(const float* __restrict__ x, __half* __restrict__ o) {
    int i = blockIdx.x * blockDim.x + threadIdx.x;
    float4 v = ((const float4*)x)[i];
    uint2 p;
    p.x = packh2(v.x, v.y);
    p.y = packh2(v.z, v.w);
    ((uint2*)o)[i] = p;
}

#define UQ (NQ_ * D_ / 4)
#define UK (NKV_ * D_ / 4)
__global__ void cvt_w_all(const int* __restrict__ wq, const int* __restrict__ wk,
                          const int* __restrict__ wv, const int* __restrict__ wo) {
    int i = blockIdx.x * blockDim.x + threadIdx.x;
    const int* src;
    __half* dst;
    int k;
    if (i < UQ)                    { src = wq; dst = g_wq16; k = i; }
    else if (i < UQ + UK)          { src = wk; dst = g_wk16; k = i - UQ; }
    else if (i < UQ + 2 * UK)      { src = wv; dst = g_wv16; k = i - UQ - UK; }
    else                           { src = wo; dst = g_wo16; k = i - UQ - 2 * UK; }
    int4 v = ((const int4*)src)[k];
    uint2 p;
    p.x = packh2((float)v.x, (float)v.y);
    p.y = packh2((float)v.z, (float)v.w);
    ((uint2*)dst)[k] = p;
}

// ---------------- shared GEMM mainloop (32x64 warp tiles, fp16) -----------
#define GBK       64
#define GCHUNK    (D_ / GBK)          // 32
#define GTILE_B   16384               // 128 rows x 128B
#define GSTAGE_B  (2 * GTILE_B)       // A, W
#define GSTG      3
#define GSMEM_DYN (GSTG * GSTAGE_B + 1024)
#define EPAD      132                 // epilogue smem row stride (floats)

__device__ __forceinline__ void g_load_chunk(
    uint32_t tbase, int buf, int kc,
    const __half* __restrict__ A, const __half* __restrict__ W,
    int bm, int bn, int tid) {
    uint32_t st = tbase + buf * GSTAGE_B;
    const __half* Ap = A + (size_t)bm * D_ + kc * GBK;
    const __half* Wp = W + (size_t)bn * D_ + kc * GBK;
    #pragma unroll
    for (int t = 0; t < 4; t++) {
        int idx = tid + t * 256;
        int row = idx >> 3;
        int seg = idx & 7;
        uint32_t off = sw128((uint32_t)(row * 128 + seg * 16));
        size_t gofs = (size_t)row * D_ + seg * 8;
        cp16(st + off,           Ap + gofs);
        cp16(st + GTILE_B + off, Wp + gofs);
    }
    CP_COMMIT();
}

// mainloop: warp (wid&3) -> 32 M-rows, (wid>>2) -> 64 N-cols. acc[2][8][4]
__device__ __forceinline__ void mma_mainloop(
    const __half* __restrict__ A, const __half* __restrict__ W,
    uint32_t tbase, int bm, int bn, int tid, float acc[2][8][4]) {
    const int wid = tid >> 5;
    const int L = tid & 31;
    const int wm = (wid & 3) * 32;
    const int wn = (wid >> 2) * 64;

    g_load_chunk(tbase, 0, 0, A, W, bm, bn, tid);
    g_load_chunk(tbase, 1, 1, A, W, bm, bn, tid);

    const int a_row = (L & 7) + ((L >> 3) & 1) * 8;
    const int a_kb  = (L >> 4) * 16;
    const int b_row = (L & 7) + ((L >> 4) << 3);
    const int b_kb  = ((L >> 3) & 1) * 16;

    int buf = 0;
    for (int kc = 0; kc < GCHUNK; kc++) {
        CP_WAIT(1);
        __syncthreads();
        if (kc + 2 < GCHUNK) {
            int nb = buf + 2; if (nb >= GSTG) nb -= GSTG;
            g_load_chunk(tbase, nb, kc + 2, A, W, bm, bn, tid);
        } else {
            CP_COMMIT();
        }

        uint32_t st = tbase + buf * GSTAGE_B;
        #pragma unroll
        for (int ks = 0; ks < 4; ks++) {
            uint32_t ah[2][4], bb[4][4];
            #pragma unroll
            for (int mi = 0; mi < 2; mi++) {
                uint32_t off = sw128((uint32_t)((wm + mi * 16 + a_row) * 128 + ks * 32 + a_kb));
                ldm4(ah[mi], st + off);
            }
            #pragma unroll
            for (int nj = 0; nj < 4; nj++) {
                uint32_t off = sw128((uint32_t)((wn + nj * 16 + b_row) * 128 + ks * 32 + b_kb));
                ldm4(bb[nj], st + GTILE_B + off);
            }
            #pragma unroll
            for (int mi = 0; mi < 2; mi++)
                #pragma unroll
                for (int j = 0; j < 8; j++)
                    mma16816(acc[mi][j], ah[mi], &bb[j >> 1][(j & 1) * 2]);
        }
        buf++; if (buf >= GSTG) buf = 0;
    }
}

// ---------------- fused QKV projection kernel ----------------
// blockIdx.x: [0,16) Q heads, [16,24) K heads, [24,32) V heads; blockIdx.y: m tile
__global__ __launch_bounds__(256, 1)
void gemm_qkv(const __half* __restrict__ A,
              const __half* __restrict__ Wq, const __half* __restrict__ Wk,
              const __half* __restrict__ Wv,
              const float* __restrict__ sq, const float* __restrict__ sk,
              const float* __restrict__ sv,
              const float* __restrict__ qnw, const float* __restrict__ knw,
              const float* __restrict__ cosc, const float* __restrict__ sinc,
              __half* __restrict__ Q, __half* __restrict__ K, __half* __restrict__ V) {
    extern __shared__ char dyns[];
    uint32_t tbase = (smem_u32(dyns) + 1023) & ~1023u;

    const int tid = threadIdx.x;
    const int wid = tid >> 5;
    const int L = tid & 31;
    const int bx = blockIdx.x;
    const int bm = blockIdx.y * 128;

    const __half* W;
    const float* scale;
    const float* nw;
    __half* Dst;
    int mode, h, nheads;
    if (bx < 16)      { W = Wq; scale = sq; nw = qnw; Dst = Q; mode = 0; h = bx;      nheads = H_;  }
    else if (bx < 24) { W = Wk; scale = sk; nw = knw; Dst = K; mode = 1; h = bx - 16; nheads = KVH_; }
    else              { W = Wv; scale = sv; nw = knw; Dst = V; mode = 2; h = bx - 24; nheads = KVH_; }
    const int bn = h * 128;

    float acc[2][8][4] = {};
    mma_mainloop(A, W, tbase, bm, bn, tid, acc);

    // ---- epilogue: exchange acc through smem into row-major per-warp layout ----
    float* sm = (float*)(size_t)0;  // placeholder; use dyns directly
    sm = (float*)dyns;              // reuse pipeline smem (mainloop done)
    const int g = L >> 2;
    const int q = L & 3;
    {
        const int wm = (wid & 3) * 32;
        const int wn = (wid >> 2) * 64;
        __syncthreads();            // all warps done reading pipeline smem
        #pragma unroll
        for (int mi = 0; mi < 2; mi++) {
            int row = wm + mi * 16 + g;
            #pragma unroll
            for (int j = 0; j < 8; j++) {
                int col = wn + j * 8 + 2 * q;
                *(float2*)&sm[row * EPAD + col] = make_float2(acc[mi][j][0], acc[mi][j][1]);
                *(float2*)&sm[(row + 8) * EPAD + col] = make_float2(acc[mi][j][2], acc[mi][j][3]);
            }
        }
        __syncthreads();
    }

    // each warp now owns rows wid*16+g, +8 across the full 128 cols
    float eacc[16][4];
    const int r0l = wid * 16 + g;
    #pragma unroll
    for (int j = 0; j < 16; j++) {
        int c = j * 8 + 2 * q;
        float2 v0 = *(float2*)&sm[r0l * EPAD + c];
        float2 v1 = *(float2*)&sm[(r0l + 8) * EPAD + c];
        eacc[j][0] = v0.x; eacc[j][1] = v0.y;
        eacc[j][2] = v1.x; eacc[j][3] = v1.y;
    }

    const int r0 = bm + r0l;
    const int r1 = r0 + 8;

    float ss0 = 0.0f, ss1 = 0.0f;
    #pragma unroll
    for (int j = 0; j < 16; j++) {
        int c = j * 8 + 2 * q;
        float s0 = __ldg(&scale[bn + c]);
        float s1 = __ldg(&scale[bn + c + 1]);
        eacc[j][0] *= s0; eacc[j][1] *= s1;
        eacc[j][2] *= s0; eacc[j][3] *= s1;
        ss0 += eacc[j][0] * eacc[j][0] + eacc[j][1] * eacc[j][1];
        ss1 += eacc[j][2] * eacc[j][2] + eacc[j][3] * eacc[j][3];
    }

    const int b = r0 >> 11;
    const int s0 = r0 & 2047;
    const int s1 = s0 + 8;
    size_t base0 = ((size_t)(b * nheads + h) * S_ + s0) * HD_;
    size_t base1 = ((size_t)(b * nheads + h) * S_ + s1) * HD_;

    if (mode == 2) {                        // V: plain fp16 convert
        #pragma unroll
        for (int j = 0; j < 16; j++) {
            int c = j * 8 + 2 * q;
            *(uint32_t*)&Dst[base0 + c] = packh2(eacc[j][0], eacc[j][1]);
            *(uint32_t*)&Dst[base1 + c] = packh2(eacc[j][2], eacc[j][3]);
        }
        return;
    }

    // Q/K: RMSNorm + RoPE
    ss0 += __shfl_xor_sync(0xffffffffu, ss0, 1);
    ss0 += __shfl_xor_sync(0xffffffffu, ss0, 2);
    ss1 += __shfl_xor_sync(0xffffffffu, ss1, 1);
    ss1 += __shfl_xor_sync(0xffffffffu, ss1, 2);
    float rms0 = rsqrtf(ss0 * (1.0f / HD_) + EPS_);
    float rms1 = rsqrtf(ss1 * (1.0f / HD_) + EPS_);

    #pragma unroll
    for (int j = 0; j < 8; j++) {
        int c = j * 8 + 2 * q;
        int cp = c + 64;
        float w0a = __ldg(&nw[c]),  w0b = __ldg(&nw[c + 1]);
        float wpa = __ldg(&nw[cp]), wpb = __ldg(&nw[cp + 1]);
        float2 c0 = *(const float2*)&cosc[(size_t)s0 * HD_ + c];
        float2 n0 = *(const float2*)&sinc[(size_t)s0 * HD_ + c];
        float2 c1 = *(const float2*)&cosc[(size_t)s1 * HD_ + c];
        float2 n1 = *(const float2*)&sinc[(size_t)s1 * HD_ + c];

        float xa = eacc[j][0] * rms0 * w0a,     xb = eacc[j][1] * rms0 * w0b;
        float ya = eacc[j + 8][0] * rms0 * wpa, yb = eacc[j + 8][1] * rms0 * wpb;
        *(uint32_t*)&Dst[base0 + c]  = packh2(xa * c0.x - ya * n0.x, xb * c0.y - yb * n0.y);
        *(uint32_t*)&Dst[base0 + cp] = packh2(ya * c0.x + xa * n0.x, yb * c0.y + xb * n0.y);

        xa = eacc[j][2] * rms1 * w0a;     xb = eacc[j][3] * rms1 * w0b;
        ya = eacc[j + 8][2] * rms1 * wpa; yb = eacc[j + 8][3] * rms1 * wpb;
        *(uint32_t*)&Dst[base1 + c]  = packh2(xa * c1.x - ya * n1.x, xb * c1.y - yb * n1.y);
        *(uint32_t*)&Dst[base1 + cp] = packh2(ya * c1.x + xa * n1.x, yb * c1.y + xb * n1.y);
    }
}

// ---------------- O projection kernel (direct fp32 store) ----------------
__global__ __launch_bounds__(256, 1)
void gemm_o(const __half* __restrict__ A, const __half* __restrict__ W,
            const float* __restrict__ scale, float* __restrict__ C, int N) {
    extern __shared__ char dyns[];
    uint32_t tbase = (smem_u32(dyns) + 1023) & ~1023u;

    const int tid = threadIdx.x;
    const int wid = tid >> 5;
    const int L = tid & 31;
    const int bm = blockIdx.y * 128;
    const int bn = blockIdx.x * 128;
    const int wm = (wid & 3) * 32;
    const int wn = (wid >> 2) * 64;

    float acc[2][8][4] = {};
    mma_mainloop(A, W, tbase, bm, bn, tid, acc);

    const int g = L >> 2;
    const int q = L & 3;
    #pragma unroll
    for (int mi = 0; mi < 2; mi++) {
        #pragma unroll
        for (int j = 0; j < 8; j++) {
            int col = bn + wn + j * 8 + q * 2;
            float s0 = __ldg(&scale[col]);
            float s1 = __ldg(&scale[col + 1]);
            int r0 = bm + wm + mi * 16 + g;
            *(float2*)&C[(size_t)r0 * N + col] =
                make_float2(acc[mi][j][0] * s0, acc[mi][j][1] * s1);
            *(float2*)&C[(size_t)(r0 + 8) * N + col] =
                make_float2(acc[mi][j][2] * s0, acc[mi][j][3] * s1);
        }
    }
}

// ---------------- fp16 tensor-core flash attention (causal, GQA) -----------
#define BQA 128
#define BKVA 64
#define AQ_BYTES   32768
#define AKV_STAGE  32768
#define ASMEM (AQ_BYTES + 2 * AKV_STAGE)   // 96KB

__device__ __forceinline__ void a_load_kv(uint32_t kvbase, int buf, int kt, int nkv,
                                          size_t kvoff, int tid) {
    if (kt < nkv) {
        int k0 = kt * BKVA;
        uint32_t st = kvbase + buf * AKV_STAGE;
        #pragma unroll
        for (int t = 0; t < 4; t++) {
            int idx = tid + t * 256;
            int row = idx >> 4;
            int ch = idx & 15;
            uint32_t off = sw256((uint32_t)(row * 256 + ch * 16));
            size_t gi = kvoff + (size_t)(k0 + row) * HD_ + ch * 8;
            cp16(st + off,         g_K16 + gi);
            cp16(st + 16384 + off, g_V16 + gi);
        }
    }
    CP_COMMIT();
}

__global__ __launch_bounds__(256, 1)
void attn_mma() {
    extern __shared__ char smraw[];
    uint32_t sb = smem_u32(smraw);
    const int tid = threadIdx.x;
    const int wid = tid >> 5;
    const int L = tid & 31;
    const int g = L >> 2;
    const int qd = L & 3;

    const int qt = (int)gridDim.x - 1 - (int)blockIdx.x;
    const int bh = blockIdx.y;
    const int b = bh >> 4;
    const int h = bh & 15;
    const int kvh = h >> 1;
    const int q0 = qt * BQA;
    const int nkv = 2 * qt + 2;
    const int wm = wid * 16;

    const uint32_t Q_s = sb;
    const uint32_t kvbase = sb + AQ_BYTES;

    const __half* Qg = g_Q16 + ((size_t)bh * S_ + q0) * HD_;
    const size_t kvoff = (size_t)(b * KVH_ + kvh) * S_ * HD_;

    #pragma unroll
    for (int t = 0; t < 8; t++) {
        int idx = tid + t * 256;
        int row = idx >> 4;
        int ch = idx & 15;
        uint32_t off = sw256((uint32_t)(row * 256 + ch * 16));
        cp16(Q_s + off, Qg + (size_t)row * HD_ + ch * 8);
    }
    a_load_kv(kvbase, 0, 0, nkv, kvoff, tid);
    a_load_kv(kvbase, 1, 1, nkv, kvoff, tid);

    float m0 = -1e30f, m1 = -1e30f, l0 = 0.0f, l1 = 0.0f;
    float oa[16][4] = {};
    const float sc = 0.08838834764831845f;

    for (int kt = 0; kt < nkv; kt++) {
        CP_WAIT(1);
        __syncthreads();
        const int k0 = kt * BKVA;
        const int buf = kt & 1;
        if (k0 <= q0 + wm + 15) {
            uint32_t st = kvbase + buf * AKV_STAGE;
            uint32_t Kh = st, Vh = st + 16384;

            float sa[8][4] = {};
            const uint32_t a_part = (uint32_t)((L & 15) * 256 + ((L >> 4) << 4));
            const uint32_t b_row  = (uint32_t)((L & 7) + ((L >> 4) << 3));
            const uint32_t b_kb   = (uint32_t)(((L >> 3) & 1) * 16);
            #pragma unroll
            for (int k16 = 0; k16 < 8; k16++) {
                uint32_t qh[4];
                uint32_t aoff = sw256((uint32_t)(wm * 256 + k16 * 32) + a_part);
                ldm4(qh, Q_s + aoff);
                #pragma unroll
                for (int n16 = 0; n16 < 4; n16++) {
                    uint32_t boff = sw256((uint32_t)((n16 * 16 + b_row) * 256 + k16 * 32 + b_kb));
                    uint32_t kh4[4];
                    ldm4(kh4, Kh + boff);
                    mma16816(sa[n16 * 2],     qh, &kh4[0]);
                    mma16816(sa[n16 * 2 + 1], qh, &kh4[2]);
                }
            }

            const int r0 = q0 + wm + g;
            const int r1 = r0 + 8;
            const bool needmask = (k0 + 63 > q0 + wm);
            #pragma unroll
            for (int t = 0; t < 8; t++) {
                #pragma unroll
                for (int c = 0; c < 4; c++) {
                    float v = sa[t][c] * sc;
                    if (needmask) {
                        int col = k0 + t * 8 + 2 * qd + (c & 1);
                        int row = (c < 2) ? r0 : r1;
                        if (col > row) v = -1e30f;
                    }
                    sa[t][c] = v;
                }
            }

            float mx0 = -1e30f, mx1 = -1e30f;
            #pragma unroll
            for (int t = 0; t < 8; t++) {
                mx0 = fmaxf(mx0, fmaxf(sa[t][0], sa[t][1]));
                mx1 = fmaxf(mx1, fmaxf(sa[t][2], sa[t][3]));
            }
            mx0 = fmaxf(mx0, __shfl_xor_sync(0xffffffffu, mx0, 1));
            mx0 = fmaxf(mx0, __shfl_xor_sync(0xffffffffu, mx0, 2));
            mx1 = fmaxf(mx1, __shfl_xor_sync(0xffffffffu, mx1, 1));
            mx1 = fmaxf(mx1, __shfl_xor_sync(0xffffffffu, mx1, 2));
            float nm0 = fmaxf(m0, mx0), nm1 = fmaxf(m1, mx1);
            float al0 = __expf(m0 - nm0), al1 = __expf(m1 - nm1);
            m0 = nm0; m1 = nm1;
            float rs0 = 0.0f, rs1 = 0.0f;
            #pragma unroll
            for (int t = 0; t < 8; t++) {
                float p0 = __expf(sa[t][0] - m0);
                float p1 = __expf(sa[t][1] - m0);
                float p2 = __expf(sa[t][2] - m1);
                float p3 = __expf(sa[t][3] - m1);
                sa[t][0] = p0; sa[t][1] = p1; sa[t][2] = p2; sa[t][3] = p3;
                rs0 += p0 + p1; rs1 += p2 + p3;
            }
            rs0 += __shfl_xor_sync(0xffffffffu, rs0, 1);
            rs0 += __shfl_xor_sync(0xffffffffu, rs0, 2);
            rs1 += __shfl_xor_sync(0xffffffffu, rs1, 1);
            rs1 += __shfl_xor_sync(0xffffffffu, rs1, 2);
            l0 = l0 * al0 + rs0;
            l1 = l1 * al1 + rs1;
            #pragma unroll
            for (int nt = 0; nt < 16; nt++) {
                oa[nt][0] *= al0; oa[nt][1] *= al0;
                oa[nt][2] *= al1; oa[nt][3] *= al1;
            }

            const uint32_t v_row = (uint32_t)((L & 7) + ((L >> 3) & 1) * 8);
            const uint32_t v_cb  = (uint32_t)((L >> 4) << 4);
            #pragma unroll
            for (int kk = 0; kk < 4; kk++) {
                const int t0 = 2 * kk, t1 = t0 + 1;
                uint32_t ph[4];
                ph[0] = packh2(sa[t0][0], sa[t0][1]);
                ph[1] = packh2(sa[t0][2], sa[t0][3]);
                ph[2] = packh2(sa[t1][0], sa[t1][1]);
                ph[3] = packh2(sa[t1][2], sa[t1][3]);
                #pragma unroll
                for (int n16 = 0; n16 < 8; n16++) {
                    uint32_t voff = sw256((uint32_t)((kk * 16 + v_row) * 256 + n16 * 32) + v_cb);
                    uint32_t vh4[4];
                    ldm4t(vh4, Vh + voff);
                    mma16816(oa[n16 * 2],     ph, &vh4[0]);
                    mma16816(oa[n16 * 2 + 1], ph, &vh4[2]);
                }
            }
        }
        __syncthreads();
        a_load_kv(kvbase, buf, kt + 2, nkv, kvoff, tid);
    }

    float inv0 = 1.0f / l0, inv1 = 1.0f / l1;
    const int r0 = q0 + wm + g;
    const int r1 = r0 + 8;
    size_t base0 = ((size_t)(b * S_) + r0) * NQ_ + h * HD_;
    size_t base1 = ((size_t)(b * S_) + r1) * NQ_ + h * HD_;
    #pragma unroll
    for (int nt = 0; nt < 16; nt++) {
        int c = nt * 8 + 2 * qd;
        *(uint32_t*)&g_a16[base0 + c] = packh2(oa[nt][0] * inv0, oa[nt][1] * inv0);
        *(uint32_t*)&g_a16[base1 + c] = packh2(oa[nt][2] * inv1, oa[nt][3] * inv1);
    }
}

// ---------------- launch ----------------
extern "C" void kernel_launch(void* const* d_in, const int* in_sizes, int n_in,
                              void* d_out, int out_size) {
    const float* x    = (const float*)d_in[0];
    const int*   wq   = (const int*)  d_in[1];
    const float* wqs  = (const float*)d_in[2];
    const int*   wk   = (const int*)  d_in[3];
    const float* wks  = (const float*)d_in[4];
    const int*   wv   = (const int*)  d_in[5];
    const float* wvs  = (const float*)d_in[6];
    const int*   wo   = (const int*)  d_in[7];
    const float* wos  = (const float*)d_in[8];
    const float* qnw  = (const float*)d_in[9];
    const float* knw  = (const float*)d_in[10];
    const float* cosc = (const float*)d_in[11];
    const float* sinc = (const float*)d_in[12];
    float* out = (float*)d_out;

    __half *x16, *a16, *wq16, *wk16, *wv16, *wo16, *Q16, *K16, *V16;
    cudaGetSymbolAddress((void**)&x16,  g_x16);
    cudaGetSymbolAddress((void**)&a16,  g_a16);
    cudaGetSymbolAddress((void**)&wq16, g_wq16);
    cudaGetSymbolAddress((void**)&wk16, g_wk16);
    cudaGetSymbolAddress((void**)&wv16, g_wv16);
    cudaGetSymbolAddress((void**)&wo16, g_wo16);
    cudaGetSymbolAddress((void**)&Q16,  g_Q16);
    cudaGetSymbolAddress((void**)&K16,  g_K16);
    cudaGetSymbolAddress((void**)&V16,  g_V16);

    cvt_x_kernel<<<(M_ * D_ / 4) / 256, 256>>>(x, x16);
    cvt_w_all<<<(2 * UQ + 2 * UK) / 256, 256>>>(wq, wk, wv, wo);

    cudaFuncSetAttribute(gemm_qkv, cudaFuncAttributeMaxDynamicSharedMemorySize, GSMEM_DYN);
    cudaFuncSetAttribute(gemm_o,   cudaFuncAttributeMaxDynamicSharedMemorySize, GSMEM_DYN);

    // fused QKV projections (one launch, 1024 CTAs)
    gemm_qkv<<<dim3(32, M_ / 128), 256, GSMEM_DYN>>>(
        x16, wq16, wk16, wv16, wqs, wks, wvs, qnw, knw, cosc, sinc, Q16, K16, V16);

    cudaFuncSetAttribute(attn_mma, cudaFuncAttributeMaxDynamicSharedMemorySize, ASMEM);
    attn_mma<<<dim3(S_ / BQA, B_ * H_), 256, ASMEM>>>();

    // O projection straight into d_out
    gemm_o<<<dim3(D_ / 128, M_ / 128), 256, GSMEM_DYN>>>(a16, wo16, wos, out, D_);
}

// round 9
// speedup vs baseline: 4.7028x; 1.1762x over previous
#include <cuda_runtime.h>
#include <cuda_fp16.h>
#include <math.h>
#include <stdint.h>

#define B_   2
#define S_   2048
#define D_   2048
#define H_   16
#define KVH_ 8
#define HD_  128
#define M_   (B_ * S_)          // 4096
#define NQ_  (H_ * HD_)         // 2048
#define NKV_ (KVH_ * HD_)       // 1024
#define EPS_ 1e-6f
#define SC_  0.08838834764831845f   // 1/sqrt(128)

// ---------------- scratch (device globals, allocation-free) ----------------
__device__ __align__(256) __half g_x16[M_ * D_];
__device__ __align__(256) __half g_a16[M_ * NQ_];
__device__ __align__(256) __half g_wq16[NQ_ * D_];
__device__ __align__(256) __half g_wk16[NKV_ * D_];
__device__ __align__(256) __half g_wv16[NKV_ * D_];
__device__ __align__(256) __half g_wo16[D_ * NQ_];
__device__ __align__(256) __half g_Q16[M_ * NQ_];
__device__ __align__(256) __half g_K16[M_ * NKV_];
__device__ __align__(256) __half g_V16[M_ * NKV_];

// ---------------- PTX helpers (baseline PTX only) ----------------
__device__ __forceinline__ uint32_t smem_u32(const void* p) {
    uint32_t a;
    asm("{ .reg .u64 t; cvta.to.shared.u64 t, %1; cvt.u32.u64 %0, t; }" : "=r"(a) : "l"(p));
    return a;
}
__device__ __forceinline__ void cp16(uint32_t s, const void* g) {
    asm volatile("cp.async.cg.shared.global [%0], [%1], 16;" :: "r"(s), "l"(g));
}
#define CP_COMMIT() asm volatile("cp.async.commit_group;" ::: "memory")
#define CP_WAIT(n)  asm volatile("cp.async.wait_group %0;" :: "n"(n) : "memory")

__device__ __forceinline__ void ldm4(uint32_t* r, uint32_t addr) {
    asm volatile("ldmatrix.sync.aligned.m8n8.x4.shared.b16 {%0,%1,%2,%3}, [%4];"
                 : "=r"(r[0]), "=r"(r[1]), "=r"(r[2]), "=r"(r[3]) : "r"(addr));
}
__device__ __forceinline__ void ldm4t(uint32_t* r, uint32_t addr) {
    asm volatile("ldmatrix.sync.aligned.m8n8.x4.trans.shared.b16 {%0,%1,%2,%3}, [%4];"
                 : "=r"(r[0]), "=r"(r[1]), "=r"(r[2]), "=r"(r[3]) : "r"(addr));
}
__device__ __forceinline__ void mma16816(float* c, const uint32_t* a, const uint32_t* b) {
    asm volatile("mma.sync.aligned.m16n8k16.row.col.f32.f16.f16.f32 "
                 "{%0,%1,%2,%3}, {%4,%5,%6,%7}, {%8,%9}, {%0,%1,%2,%3};"
                 : "+f"(c[0]), "+f"(c[1]), "+f"(c[2]), "+f"(c[3])
                 : "r"(a[0]), "r"(a[1]), "r"(a[2]), "r"(a[3]), "r"(b[0]), "r"(b[1]));
}

__device__ __forceinline__ uint32_t sw128(uint32_t off) { return off ^ ((off >> 3) & 0x70); }
__device__ __forceinline__ uint32_t sw256(uint32_t off) { return off ^ ((off >> 4) & 0x70); }

__device__ __forceinline__ uint32_t packh2(float a, float b) {
    __half2 h = __floats2half2_rn(a, b);
    return *(uint32_t*)&h;
}

// ---------------- conversion kernels ----------------
__global__ void cvt_x_kernel(const float* __restrict__ x, __half* __restrict__ o) {
    int i = blockIdx.x * blockDim.x + threadIdx.x;
    float4 v = ((const float4*)x)[i];
    uint2 p;
    p.x = packh2(v.x, v.y);
    p.y = packh2(v.z, v.w);
    ((uint2*)o)[i] = p;
}

#define UQ (NQ_ * D_ / 4)
#define UK (NKV_ * D_ / 4)
__global__ void cvt_w_all(const int* __restrict__ wq, const int* __restrict__ wk,
                          const int* __restrict__ wv, const int* __restrict__ wo) {
    int i = blockIdx.x * blockDim.x + threadIdx.x;
    const int* src;
    __half* dst;
    int k;
    if (i < UQ)                    { src = wq; dst = g_wq16; k = i; }
    else if (i < UQ + UK)          { src = wk; dst = g_wk16; k = i - UQ; }
    else if (i < UQ + 2 * UK)      { src = wv; dst = g_wv16; k = i - UQ - UK; }
    else                           { src = wo; dst = g_wo16; k = i - UQ - 2 * UK; }
    int4 v = ((const int4*)src)[k];
    uint2 p;
    p.x = packh2((float)v.x, (float)v.y);
    p.y = packh2((float)v.z, (float)v.w);
    ((uint2*)dst)[k] = p;
}

// ---------------- shared GEMM mainloop (32x64 warp tiles, fp16) -----------
#define GBK       64
#define GCHUNK    (D_ / GBK)          // 32
#define GTILE_B   16384               // 128 rows x 128B
#define GSTAGE_B  (2 * GTILE_B)       // A, W
#define GSTG      3
#define GSMEM_DYN (GSTG * GSTAGE_B + 1024)
#define EPAD      132                 // epilogue smem row stride (floats)

__device__ __forceinline__ void g_load_chunk(
    uint32_t tbase, int buf, int kc,
    const __half* __restrict__ A, const __half* __restrict__ W,
    int bm, int bn, int tid) {
    uint32_t st = tbase + buf * GSTAGE_B;
    const __half* Ap = A + (size_t)bm * D_ + kc * GBK;
    const __half* Wp = W + (size_t)bn * D_ + kc * GBK;
    #pragma unroll
    for (int t = 0; t < 4; t++) {
        int idx = tid + t * 256;
        int row = idx >> 3;
        int seg = idx & 7;
        uint32_t off = sw128((uint32_t)(row * 128 + seg * 16));
        size_t gofs = (size_t)row * D_ + seg * 8;
        cp16(st + off,           Ap + gofs);
        cp16(st + GTILE_B + off, Wp + gofs);
    }
    CP_COMMIT();
}

__device__ __forceinline__ void mma_mainloop(
    const __half* __restrict__ A, const __half* __restrict__ W,
    uint32_t tbase, int bm, int bn, int tid, float acc[2][8][4]) {
    const int wid = tid >> 5;
    const int L = tid & 31;
    const int wm = (wid & 3) * 32;
    const int wn = (wid >> 2) * 64;

    g_load_chunk(tbase, 0, 0, A, W, bm, bn, tid);
    g_load_chunk(tbase, 1, 1, A, W, bm, bn, tid);

    const int a_row = (L & 7) + ((L >> 3) & 1) * 8;
    const int a_kb  = (L >> 4) * 16;
    const int b_row = (L & 7) + ((L >> 4) << 3);
    const int b_kb  = ((L >> 3) & 1) * 16;

    int buf = 0;
    for (int kc = 0; kc < GCHUNK; kc++) {
        CP_WAIT(1);
        __syncthreads();
        if (kc + 2 < GCHUNK) {
            int nb = buf + 2; if (nb >= GSTG) nb -= GSTG;
            g_load_chunk(tbase, nb, kc + 2, A, W, bm, bn, tid);
        } else {
            CP_COMMIT();
        }

        uint32_t st = tbase + buf * GSTAGE_B;
        #pragma unroll
        for (int ks = 0; ks < 4; ks++) {
            uint32_t ah[2][4], bb[4][4];
            #pragma unroll
            for (int mi = 0; mi < 2; mi++) {
                uint32_t off = sw128((uint32_t)((wm + mi * 16 + a_row) * 128 + ks * 32 + a_kb));
                ldm4(ah[mi], st + off);
            }
            #pragma unroll
            for (int nj = 0; nj < 4; nj++) {
                uint32_t off = sw128((uint32_t)((wn + nj * 16 + b_row) * 128 + ks * 32 + b_kb));
                ldm4(bb[nj], st + GTILE_B + off);
            }
            #pragma unroll
            for (int mi = 0; mi < 2; mi++)
                #pragma unroll
                for (int j = 0; j < 8; j++)
                    mma16816(acc[mi][j], ah[mi], &bb[j >> 1][(j & 1) * 2]);
        }
        buf++; if (buf >= GSTG) buf = 0;
    }
}

// ---------------- fused QKV projection kernel ----------------
__global__ __launch_bounds__(256, 2)
void gemm_qkv(const __half* __restrict__ A,
              const __half* __restrict__ Wq, const __half* __restrict__ Wk,
              const __half* __restrict__ Wv,
              const float* __restrict__ sq, const float* __restrict__ sk,
              const float* __restrict__ sv,
              const float* __restrict__ qnw, const float* __restrict__ knw,
              const float* __restrict__ cosc, const float* __restrict__ sinc,
              __half* __restrict__ Q, __half* __restrict__ K, __half* __restrict__ V) {
    extern __shared__ char dyns[];
    uint32_t tbase = (smem_u32(dyns) + 1023) & ~1023u;

    const int tid = threadIdx.x;
    const int wid = tid >> 5;
    const int L = tid & 31;
    const int bx = blockIdx.x;
    const int bm = blockIdx.y * 128;

    const __half* W;
    const float* scale;
    const float* nw;
    __half* Dst;
    int mode, h, nheads;
    if (bx < 16)      { W = Wq; scale = sq; nw = qnw; Dst = Q; mode = 0; h = bx;      nheads = H_;  }
    else if (bx < 24) { W = Wk; scale = sk; nw = knw; Dst = K; mode = 1; h = bx - 16; nheads = KVH_; }
    else              { W = Wv; scale = sv; nw = knw; Dst = V; mode = 2; h = bx - 24; nheads = KVH_; }
    const int bn = h * 128;

    float acc[2][8][4] = {};
    mma_mainloop(A, W, tbase, bm, bn, tid, acc);

    // epilogue: exchange acc through smem into row-major per-warp layout
    float* sm = (float*)dyns;
    const int g = L >> 2;
    const int q = L & 3;
    {
        const int wm = (wid & 3) * 32;
        const int wn = (wid >> 2) * 64;
        __syncthreads();
        #pragma unroll
        for (int mi = 0; mi < 2; mi++) {
            int row = wm + mi * 16 + g;
            #pragma unroll
            for (int j = 0; j < 8; j++) {
                int col = wn + j * 8 + 2 * q;
                *(float2*)&sm[row * EPAD + col] = make_float2(acc[mi][j][0], acc[mi][j][1]);
                *(float2*)&sm[(row + 8) * EPAD + col] = make_float2(acc[mi][j][2], acc[mi][j][3]);
            }
        }
        __syncthreads();
    }

    float eacc[16][4];
    const int r0l = wid * 16 + g;
    #pragma unroll
    for (int j = 0; j < 16; j++) {
        int c = j * 8 + 2 * q;
        float2 v0 = *(float2*)&sm[r0l * EPAD + c];
        float2 v1 = *(float2*)&sm[(r0l + 8) * EPAD + c];
        eacc[j][0] = v0.x; eacc[j][1] = v0.y;
        eacc[j][2] = v1.x; eacc[j][3] = v1.y;
    }

    const int r0 = bm + r0l;

    float ss0 = 0.0f, ss1 = 0.0f;
    #pragma unroll
    for (int j = 0; j < 16; j++) {
        int c = j * 8 + 2 * q;
        float s0 = __ldg(&scale[bn + c]);
        float s1 = __ldg(&scale[bn + c + 1]);
        eacc[j][0] *= s0; eacc[j][1] *= s1;
        eacc[j][2] *= s0; eacc[j][3] *= s1;
        ss0 += eacc[j][0] * eacc[j][0] + eacc[j][1] * eacc[j][1];
        ss1 += eacc[j][2] * eacc[j][2] + eacc[j][3] * eacc[j][3];
    }

    const int b = r0 >> 11;
    const int s0 = r0 & 2047;
    const int s1 = s0 + 8;
    size_t base0 = ((size_t)(b * nheads + h) * S_ + s0) * HD_;
    size_t base1 = ((size_t)(b * nheads + h) * S_ + s1) * HD_;

    if (mode == 2) {                        // V: plain fp16 convert
        #pragma unroll
        for (int j = 0; j < 16; j++) {
            int c = j * 8 + 2 * q;
            *(uint32_t*)&Dst[base0 + c] = packh2(eacc[j][0], eacc[j][1]);
            *(uint32_t*)&Dst[base1 + c] = packh2(eacc[j][2], eacc[j][3]);
        }
        return;
    }

    // Q/K: RMSNorm + RoPE (Q additionally pre-scaled by 1/sqrt(HD))
    ss0 += __shfl_xor_sync(0xffffffffu, ss0, 1);
    ss0 += __shfl_xor_sync(0xffffffffu, ss0, 2);
    ss1 += __shfl_xor_sync(0xffffffffu, ss1, 1);
    ss1 += __shfl_xor_sync(0xffffffffu, ss1, 2);
    float rms0 = rsqrtf(ss0 * (1.0f / HD_) + EPS_);
    float rms1 = rsqrtf(ss1 * (1.0f / HD_) + EPS_);
    if (mode == 0) { rms0 *= SC_; rms1 *= SC_; }   // fold attention scale into Q

    #pragma unroll
    for (int j = 0; j < 8; j++) {
        int c = j * 8 + 2 * q;
        int cp = c + 64;
        float w0a = __ldg(&nw[c]),  w0b = __ldg(&nw[c + 1]);
        float wpa = __ldg(&nw[cp]), wpb = __ldg(&nw[cp + 1]);
        float2 c0 = *(const float2*)&cosc[(size_t)s0 * HD_ + c];
        float2 n0 = *(const float2*)&sinc[(size_t)s0 * HD_ + c];
        float2 c1 = *(const float2*)&cosc[(size_t)s1 * HD_ + c];
        float2 n1 = *(const float2*)&sinc[(size_t)s1 * HD_ + c];

        float xa = eacc[j][0] * rms0 * w0a,     xb = eacc[j][1] * rms0 * w0b;
        float ya = eacc[j + 8][0] * rms0 * wpa, yb = eacc[j + 8][1] * rms0 * wpb;
        *(uint32_t*)&Dst[base0 + c]  = packh2(xa * c0.x - ya * n0.x, xb * c0.y - yb * n0.y);
        *(uint32_t*)&Dst[base0 + cp] = packh2(ya * c0.x + xa * n0.x, yb * c0.y + xb * n0.y);

        xa = eacc[j][2] * rms1 * w0a;     xb = eacc[j][3] * rms1 * w0b;
        ya = eacc[j + 8][2] * rms1 * wpa; yb = eacc[j + 8][3] * rms1 * wpb;
        *(uint32_t*)&Dst[base1 + c]  = packh2(xa * c1.x - ya * n1.x, xb * c1.y - yb * n1.y);
        *(uint32_t*)&Dst[base1 + cp] = packh2(ya * c1.x + xa * n1.x, yb * c1.y + xb * n1.y);
    }
}

// ---------------- O projection kernel (direct fp32 store) ----------------
__global__ __launch_bounds__(256, 2)
void gemm_o(const __half* __restrict__ A, const __half* __restrict__ W,
            const float* __restrict__ scale, float* __restrict__ C, int N) {
    extern __shared__ char dyns[];
    uint32_t tbase = (smem_u32(dyns) + 1023) & ~1023u;

    const int tid = threadIdx.x;
    const int wid = tid >> 5;
    const int L = tid & 31;
    const int bm = blockIdx.y * 128;
    const int bn = blockIdx.x * 128;
    const int wm = (wid & 3) * 32;
    const int wn = (wid >> 2) * 64;

    float acc[2][8][4] = {};
    mma_mainloop(A, W, tbase, bm, bn, tid, acc);

    const int g = L >> 2;
    const int q = L & 3;
    #pragma unroll
    for (int mi = 0; mi < 2; mi++) {
        #pragma unroll
        for (int j = 0; j < 8; j++) {
            int col = bn + wn + j * 8 + q * 2;
            float s0 = __ldg(&scale[col]);
            float s1 = __ldg(&scale[col + 1]);
            int r0 = bm + wm + mi * 16 + g;
            *(float2*)&C[(size_t)r0 * N + col] =
                make_float2(acc[mi][j][0] * s0, acc[mi][j][1] * s1);
            *(float2*)&C[(size_t)(r0 + 8) * N + col] =
                make_float2(acc[mi][j][2] * s0, acc[mi][j][3] * s1);
        }
    }
}

// ---------------- fp16 tensor-core flash attention (causal, GQA) -----------
#define BQA 128
#define BKVA 64
#define AQ_BYTES   32768
#define AKV_STAGE  32768
#define ASMEM (AQ_BYTES + 2 * AKV_STAGE)   // 96KB

__device__ __forceinline__ void a_load_kv(uint32_t kvbase, int buf, int kt, int nkv,
                                          size_t kvoff, int tid) {
    if (kt < nkv) {
        int k0 = kt * BKVA;
        uint32_t st = kvbase + buf * AKV_STAGE;
        #pragma unroll
        for (int t = 0; t < 4; t++) {
            int idx = tid + t * 256;
            int row = idx >> 4;
            int ch = idx & 15;
            uint32_t off = sw256((uint32_t)(row * 256 + ch * 16));
            size_t gi = kvoff + (size_t)(k0 + row) * HD_ + ch * 8;
            cp16(st + off,         g_K16 + gi);
            cp16(st + 16384 + off, g_V16 + gi);
        }
    }
    CP_COMMIT();
}

__global__ __launch_bounds__(256, 1)
void attn_mma() {
    extern __shared__ char smraw[];
    uint32_t sb = smem_u32(smraw);
    const int tid = threadIdx.x;
    const int wid = tid >> 5;
    const int L = tid & 31;
    const int g = L >> 2;
    const int qd = L & 3;

    const int qt = (int)gridDim.x - 1 - (int)blockIdx.x;
    const int bh = blockIdx.y;
    const int b = bh >> 4;
    const int h = bh & 15;
    const int kvh = h >> 1;
    const int q0 = qt * BQA;
    const int nkv = 2 * qt + 2;
    const int wm = wid * 16;

    const uint32_t Q_s = sb;
    const uint32_t kvbase = sb + AQ_BYTES;

    const __half* Qg = g_Q16 + ((size_t)bh * S_ + q0) * HD_;
    const size_t kvoff = (size_t)(b * KVH_ + kvh) * S_ * HD_;

    #pragma unroll
    for (int t = 0; t < 8; t++) {
        int idx = tid + t * 256;
        int row = idx >> 4;
        int ch = idx & 15;
        uint32_t off = sw256((uint32_t)(row * 256 + ch * 16));
        cp16(Q_s + off, Qg + (size_t)row * HD_ + ch * 8);
    }
    a_load_kv(kvbase, 0, 0, nkv, kvoff, tid);   // group0 = Q + KV0
    a_load_kv(kvbase, 1, 1, nkv, kvoff, tid);   // group1 = KV1

    // hoist Q fragments into registers (reused across all KV tiles)
    CP_WAIT(1);
    __syncthreads();
    uint32_t qf[8][4];
    {
        const uint32_t a_part = (uint32_t)((L & 15) * 256 + ((L >> 4) << 4));
        #pragma unroll
        for (int k16 = 0; k16 < 8; k16++)
            ldm4(qf[k16], Q_s + sw256((uint32_t)(wm * 256 + k16 * 32) + a_part));
    }

    float m0 = -1e30f, m1 = -1e30f, l0 = 0.0f, l1 = 0.0f;
    float oa[16][4] = {};

    for (int kt = 0; kt < nkv; kt++) {
        CP_WAIT(1);
        __syncthreads();
        const int k0 = kt * BKVA;
        const int buf = kt & 1;
        if (k0 <= q0 + wm + 15) {
            uint32_t st = kvbase + buf * AKV_STAGE;
            uint32_t Kh = st, Vh = st + 16384;

            float sa[8][4] = {};
            const uint32_t b_row  = (uint32_t)((L & 7) + ((L >> 4) << 3));
            const uint32_t b_kb   = (uint32_t)(((L >> 3) & 1) * 16);
            #pragma unroll
            for (int k16 = 0; k16 < 8; k16++) {
                #pragma unroll
                for (int n16 = 0; n16 < 4; n16++) {
                    uint32_t boff = sw256((uint32_t)((n16 * 16 + b_row) * 256 + k16 * 32 + b_kb));
                    uint32_t kh4[4];
                    ldm4(kh4, Kh + boff);
                    mma16816(sa[n16 * 2],     qf[k16], &kh4[0]);
                    mma16816(sa[n16 * 2 + 1], qf[k16], &kh4[2]);
                }
            }

            const int r0 = q0 + wm + g;
            const int r1 = r0 + 8;
            // causal mask only needed on diagonal tiles (Q pre-scaled in projection)
            if (k0 + 63 > q0 + wm) {
                #pragma unroll
                for (int t = 0; t < 8; t++) {
                    #pragma unroll
                    for (int c = 0; c < 4; c++) {
                        int col = k0 + t * 8 + 2 * qd + (c & 1);
                        int row = (c < 2) ? r0 : r1;
                        if (col > row) sa[t][c] = -1e30f;
                    }
                }
            }

            float mx0 = -1e30f, mx1 = -1e30f;
            #pragma unroll
            for (int t = 0; t < 8; t++) {
                mx0 = fmaxf(mx0, fmaxf(sa[t][0], sa[t][1]));
                mx1 = fmaxf(mx1, fmaxf(sa[t][2], sa[t][3]));
            }
            mx0 = fmaxf(mx0, __shfl_xor_sync(0xffffffffu, mx0, 1));
            mx0 = fmaxf(mx0, __shfl_xor_sync(0xffffffffu, mx0, 2));
            mx1 = fmaxf(mx1, __shfl_xor_sync(0xffffffffu, mx1, 1));
            mx1 = fmaxf(mx1, __shfl_xor_sync(0xffffffffu, mx1, 2));
            float nm0 = fmaxf(m0, mx0), nm1 = fmaxf(m1, mx1);
            float al0 = __expf(m0 - nm0), al1 = __expf(m1 - nm1);
            m0 = nm0; m1 = nm1;
            float rs0 = 0.0f, rs1 = 0.0f;
            #pragma unroll
            for (int t = 0; t < 8; t++) {
                float p0 = __expf(sa[t][0] - m0);
                float p1 = __expf(sa[t][1] - m0);
                float p2 = __expf(sa[t][2] - m1);
                float p3 = __expf(sa[t][3] - m1);
                sa[t][0] = p0; sa[t][1] = p1; sa[t][2] = p2; sa[t][3] = p3;
                rs0 += p0 + p1; rs1 += p2 + p3;
            }
            rs0 += __shfl_xor_sync(0xffffffffu, rs0, 1);
            rs0 += __shfl_xor_sync(0xffffffffu, rs0, 2);
            rs1 += __shfl_xor_sync(0xffffffffu, rs1, 1);
            rs1 += __shfl_xor_sync(0xffffffffu, rs1, 2);
            l0 = l0 * al0 + rs0;
            l1 = l1 * al1 + rs1;
            #pragma unroll
            for (int nt = 0; nt < 16; nt++) {
                oa[nt][0] *= al0; oa[nt][1] *= al0;
                oa[nt][2] *= al1; oa[nt][3] *= al1;
            }

            const uint32_t v_row = (uint32_t)((L & 7) + ((L >> 3) & 1) * 8);
            const uint32_t v_cb  = (uint32_t)((L >> 4) << 4);
            #pragma unroll
            for (int kk = 0; kk < 4; kk++) {
                const int t0 = 2 * kk, t1 = t0 + 1;
                uint32_t ph[4];
                ph[0] = packh2(sa[t0][0], sa[t0][1]);
                ph[1] = packh2(sa[t0][2], sa[t0][3]);
                ph[2] = packh2(sa[t1][0], sa[t1][1]);
                ph[3] = packh2(sa[t1][2], sa[t1][3]);
                #pragma unroll
                for (int n16 = 0; n16 < 8; n16++) {
                    uint32_t voff = sw256((uint32_t)((kk * 16 + v_row) * 256 + n16 * 32) + v_cb);
                    uint32_t vh4[4];
                    ldm4t(vh4, Vh + voff);
                    mma16816(oa[n16 * 2],     ph, &vh4[0]);
                    mma16816(oa[n16 * 2 + 1], ph, &vh4[2]);
                }
            }
        }
        __syncthreads();
        a_load_kv(kvbase, buf, kt + 2, nkv, kvoff, tid);
    }

    float inv0 = 1.0f / l0, inv1 = 1.0f / l1;
    const int r0 = q0 + wm + g;
    const int r1 = r0 + 8;
    size_t base0 = ((size_t)(b * S_) + r0) * NQ_ + h * HD_;
    size_t base1 = ((size_t)(b * S_) + r1) * NQ_ + h * HD_;
    #pragma unroll
    for (int nt = 0; nt < 16; nt++) {
        int c = nt * 8 + 2 * qd;
        *(uint32_t*)&g_a16[base0 + c] = packh2(oa[nt][0] * inv0, oa[nt][1] * inv0);
        *(uint32_t*)&g_a16[base1 + c] = packh2(oa[nt][2] * inv1, oa[nt][3] * inv1);
    }
}

// ---------------- launch ----------------
extern "C" void kernel_launch(void* const* d_in, const int* in_sizes, int n_in,
                              void* d_out, int out_size) {
    const float* x    = (const float*)d_in[0];
    const int*   wq   = (const int*)  d_in[1];
    const float* wqs  = (const float*)d_in[2];
    const int*   wk   = (const int*)  d_in[3];
    const float* wks  = (const float*)d_in[4];
    const int*   wv   = (const int*)  d_in[5];
    const float* wvs  = (const float*)d_in[6];
    const int*   wo   = (const int*)  d_in[7];
    const float* wos  = (const float*)d_in[8];
    const float* qnw  = (const float*)d_in[9];
    const float* knw  = (const float*)d_in[10];
    const float* cosc = (const float*)d_in[11];
    const float* sinc = (const float*)d_in[12];
    float* out = (float*)d_out;

    __half *x16, *a16, *wq16, *wk16, *wv16, *wo16, *Q16, *K16, *V16;
    cudaGetSymbolAddress((void**)&x16,  g_x16);
    cudaGetSymbolAddress((void**)&a16,  g_a16);
    cudaGetSymbolAddress((void**)&wq16, g_wq16);
    cudaGetSymbolAddress((void**)&wk16, g_wk16);
    cudaGetSymbolAddress((void**)&wv16, g_wv16);
    cudaGetSymbolAddress((void**)&wo16, g_wo16);
    cudaGetSymbolAddress((void**)&Q16,  g_Q16);
    cudaGetSymbolAddress((void**)&K16,  g_K16);
    cudaGetSymbolAddress((void**)&V16,  g_V16);

    cvt_x_kernel<<<(M_ * D_ / 4) / 256, 256>>>(x, x16);
    cvt_w_all<<<(2 * UQ + 2 * UK) / 256, 256>>>(wq, wk, wv, wo);

    cudaFuncSetAttribute(gemm_qkv, cudaFuncAttributeMaxDynamicSharedMemorySize, GSMEM_DYN);
    cudaFuncSetAttribute(gemm_o,   cudaFuncAttributeMaxDynamicSharedMemorySize, GSMEM_DYN);

    gemm_qkv<<<dim3(32, M_ / 128), 256, GSMEM_DYN>>>(
        x16, wq16, wk16, wv16, wqs, wks, wvs, qnw, knw, cosc, sinc, Q16, K16, V16);

    cudaFuncSetAttribute(attn_mma, cudaFuncAttributeMaxDynamicSharedMemorySize, ASMEM);
    attn_mma<<<dim3(S_ / BQA, B_ * H_), 256, ASMEM>>>();

    gemm_o<<<dim3(D_ / 128, M_ / 128), 256, GSMEM_DYN>>>(a16, wo16, wos, out, D_);
}

// round 10
// speedup vs baseline: 4.7814x; 1.0167x over previous
#include <cuda_runtime.h>
#include <cuda_fp16.h>
#include <math.h>
#include <stdint.h>

#define B_   2
#define S_   2048
#define D_   2048
#define H_   16
#define KVH_ 8
#define HD_  128
#define M_   (B_ * S_)          // 4096
#define NQ_  (H_ * HD_)         // 2048
#define NKV_ (KVH_ * HD_)       // 1024
#define EPS_ 1e-6f
#define SC_    0.08838834764831845f    // 1/sqrt(128)
#define LOG2E_ 1.4426950408889634f

// ---------------- scratch (device globals, allocation-free) ----------------
__device__ __align__(256) __half g_x16[M_ * D_];
__device__ __align__(256) __half g_a16[M_ * NQ_];
__device__ __align__(256) __half g_wq16[NQ_ * D_];
__device__ __align__(256) __half g_wk16[NKV_ * D_];
__device__ __align__(256) __half g_wv16[NKV_ * D_];
__device__ __align__(256) __half g_wo16[D_ * NQ_];
__device__ __align__(256) __half g_Q16[M_ * NQ_];
__device__ __align__(256) __half g_K16[M_ * NKV_];
__device__ __align__(256) __half g_V16[M_ * NKV_];

// ---------------- PTX helpers (baseline PTX only) ----------------
__device__ __forceinline__ uint32_t smem_u32(const void* p) {
    uint32_t a;
    asm("{ .reg .u64 t; cvta.to.shared.u64 t, %1; cvt.u32.u64 %0, t; }" : "=r"(a) : "l"(p));
    return a;
}
__device__ __forceinline__ void cp16(uint32_t s, const void* g) {
    asm volatile("cp.async.cg.shared.global [%0], [%1], 16;" :: "r"(s), "l"(g));
}
#define CP_COMMIT() asm volatile("cp.async.commit_group;" ::: "memory")
#define CP_WAIT(n)  asm volatile("cp.async.wait_group %0;" :: "n"(n) : "memory")

__device__ __forceinline__ void ldm4(uint32_t* r, uint32_t addr) {
    asm volatile("ldmatrix.sync.aligned.m8n8.x4.shared.b16 {%0,%1,%2,%3}, [%4];"
                 : "=r"(r[0]), "=r"(r[1]), "=r"(r[2]), "=r"(r[3]) : "r"(addr));
}
__device__ __forceinline__ void ldm4t(uint32_t* r, uint32_t addr) {
    asm volatile("ldmatrix.sync.aligned.m8n8.x4.trans.shared.b16 {%0,%1,%2,%3}, [%4];"
                 : "=r"(r[0]), "=r"(r[1]), "=r"(r[2]), "=r"(r[3]) : "r"(addr));
}
__device__ __forceinline__ void mma16816(float* c, const uint32_t* a, const uint32_t* b) {
    asm volatile("mma.sync.aligned.m16n8k16.row.col.f32.f16.f16.f32 "
                 "{%0,%1,%2,%3}, {%4,%5,%6,%7}, {%8,%9}, {%0,%1,%2,%3};"
                 : "+f"(c[0]), "+f"(c[1]), "+f"(c[2]), "+f"(c[3])
                 : "r"(a[0]), "r"(a[1]), "r"(a[2]), "r"(a[3]), "r"(b[0]), "r"(b[1]));
}

__device__ __forceinline__ uint32_t sw128(uint32_t off) { return off ^ ((off >> 3) & 0x70); }
__device__ __forceinline__ uint32_t sw256(uint32_t off) { return off ^ ((off >> 4) & 0x70); }

__device__ __forceinline__ uint32_t packh2(float a, float b) {
    __half2 h = __floats2half2_rn(a, b);
    return *(uint32_t*)&h;
}
__device__ __forceinline__ float ex2(float x) {
    float y;
    asm("ex2.approx.f32 %0, %1;" : "=f"(y) : "f"(x));
    return y;
}

// ---------------- merged conversion kernel ----------------
#define UX (M_ * D_ / 4)
#define UQ (NQ_ * D_ / 4)
#define UK (NKV_ * D_ / 4)
__global__ void cvt_all(const float* __restrict__ x,
                        const int* __restrict__ wq, const int* __restrict__ wk,
                        const int* __restrict__ wv, const int* __restrict__ wo) {
    int i = blockIdx.x * blockDim.x + threadIdx.x;
    if (i < UX) {
        float4 v = ((const float4*)x)[i];
        uint2 p;
        p.x = packh2(v.x, v.y);
        p.y = packh2(v.z, v.w);
        ((uint2*)g_x16)[i] = p;
        return;
    }
    i -= UX;
    const int* src;
    __half* dst;
    int k;
    if (i < UQ)                    { src = wq; dst = g_wq16; k = i; }
    else if (i < UQ + UK)          { src = wk; dst = g_wk16; k = i - UQ; }
    else if (i < UQ + 2 * UK)      { src = wv; dst = g_wv16; k = i - UQ - UK; }
    else                           { src = wo; dst = g_wo16; k = i - UQ - 2 * UK; }
    int4 v = ((const int4*)src)[k];
    uint2 p;
    p.x = packh2((float)v.x, (float)v.y);
    p.y = packh2((float)v.z, (float)v.w);
    ((uint2*)dst)[k] = p;
}

// ---------------- shared GEMM mainloop (32x64 warp tiles, fp16) -----------
#define GBK       64
#define GCHUNK    (D_ / GBK)          // 32
#define GTILE_B   16384               // 128 rows x 128B
#define GSTAGE_B  (2 * GTILE_B)       // A, W
#define GSTG      3
#define GSMEM_DYN (GSTG * GSTAGE_B + 1024)
#define EPAD      132

__device__ __forceinline__ void g_load_chunk(
    uint32_t tbase, int buf, int kc,
    const __half* __restrict__ A, const __half* __restrict__ W,
    int bm, int bn, int tid) {
    uint32_t st = tbase + buf * GSTAGE_B;
    const __half* Ap = A + (size_t)bm * D_ + kc * GBK;
    const __half* Wp = W + (size_t)bn * D_ + kc * GBK;
    #pragma unroll
    for (int t = 0; t < 4; t++) {
        int idx = tid + t * 256;
        int row = idx >> 3;
        int seg = idx & 7;
        uint32_t off = sw128((uint32_t)(row * 128 + seg * 16));
        size_t gofs = (size_t)row * D_ + seg * 8;
        cp16(st + off,           Ap + gofs);
        cp16(st + GTILE_B + off, Wp + gofs);
    }
    CP_COMMIT();
}

__device__ __forceinline__ void mma_mainloop(
    const __half* __restrict__ A, const __half* __restrict__ W,
    uint32_t tbase, int bm, int bn, int tid, float acc[2][8][4]) {
    const int wid = tid >> 5;
    const int L = tid & 31;
    const int wm = (wid & 3) * 32;
    const int wn = (wid >> 2) * 64;

    g_load_chunk(tbase, 0, 0, A, W, bm, bn, tid);
    g_load_chunk(tbase, 1, 1, A, W, bm, bn, tid);

    const int a_row = (L & 7) + ((L >> 3) & 1) * 8;
    const int a_kb  = (L >> 4) * 16;
    const int b_row = (L & 7) + ((L >> 4) << 3);
    const int b_kb  = ((L >> 3) & 1) * 16;

    int buf = 0;
    for (int kc = 0; kc < GCHUNK; kc++) {
        CP_WAIT(1);
        __syncthreads();
        if (kc + 2 < GCHUNK) {
            int nb = buf + 2; if (nb >= GSTG) nb -= GSTG;
            g_load_chunk(tbase, nb, kc + 2, A, W, bm, bn, tid);
        } else {
            CP_COMMIT();
        }

        uint32_t st = tbase + buf * GSTAGE_B;
        #pragma unroll
        for (int ks = 0; ks < 4; ks++) {
            uint32_t ah[2][4], bb[4][4];
            #pragma unroll
            for (int mi = 0; mi < 2; mi++) {
                uint32_t off = sw128((uint32_t)((wm + mi * 16 + a_row) * 128 + ks * 32 + a_kb));
                ldm4(ah[mi], st + off);
            }
            #pragma unroll
            for (int nj = 0; nj < 4; nj++) {
                uint32_t off = sw128((uint32_t)((wn + nj * 16 + b_row) * 128 + ks * 32 + b_kb));
                ldm4(bb[nj], st + GTILE_B + off);
            }
            #pragma unroll
            for (int mi = 0; mi < 2; mi++)
                #pragma unroll
                for (int j = 0; j < 8; j++)
                    mma16816(acc[mi][j], ah[mi], &bb[j >> 1][(j & 1) * 2]);
        }
        buf++; if (buf >= GSTG) buf = 0;
    }
}

// ---------------- fused QKV projection kernel ----------------
__global__ __launch_bounds__(256, 2)
void gemm_qkv(const __half* __restrict__ A,
              const __half* __restrict__ Wq, const __half* __restrict__ Wk,
              const __half* __restrict__ Wv,
              const float* __restrict__ sq, const float* __restrict__ sk,
              const float* __restrict__ sv,
              const float* __restrict__ qnw, const float* __restrict__ knw,
              const float* __restrict__ cosc, const float* __restrict__ sinc,
              __half* __restrict__ Q, __half* __restrict__ K, __half* __restrict__ V) {
    extern __shared__ char dyns[];
    uint32_t tbase = (smem_u32(dyns) + 1023) & ~1023u;

    const int tid = threadIdx.x;
    const int wid = tid >> 5;
    const int L = tid & 31;
    const int bx = blockIdx.x;
    const int bm = blockIdx.y * 128;

    const __half* W;
    const float* scale;
    const float* nw;
    __half* Dst;
    int mode, h, nheads;
    if (bx < 16)      { W = Wq; scale = sq; nw = qnw; Dst = Q; mode = 0; h = bx;      nheads = H_;  }
    else if (bx < 24) { W = Wk; scale = sk; nw = knw; Dst = K; mode = 1; h = bx - 16; nheads = KVH_; }
    else              { W = Wv; scale = sv; nw = knw; Dst = V; mode = 2; h = bx - 24; nheads = KVH_; }
    const int bn = h * 128;

    float acc[2][8][4] = {};
    mma_mainloop(A, W, tbase, bm, bn, tid, acc);

    // epilogue: exchange acc through smem into row-major per-warp layout
    float* sm = (float*)dyns;
    const int g = L >> 2;
    const int q = L & 3;
    {
        const int wm = (wid & 3) * 32;
        const int wn = (wid >> 2) * 64;
        __syncthreads();
        #pragma unroll
        for (int mi = 0; mi < 2; mi++) {
            int row = wm + mi * 16 + g;
            #pragma unroll
            for (int j = 0; j < 8; j++) {
                int col = wn + j * 8 + 2 * q;
                *(float2*)&sm[row * EPAD + col] = make_float2(acc[mi][j][0], acc[mi][j][1]);
                *(float2*)&sm[(row + 8) * EPAD + col] = make_float2(acc[mi][j][2], acc[mi][j][3]);
            }
        }
        __syncthreads();
    }

    float eacc[16][4];
    const int r0l = wid * 16 + g;
    #pragma unroll
    for (int j = 0; j < 16; j++) {
        int c = j * 8 + 2 * q;
        float2 v0 = *(float2*)&sm[r0l * EPAD + c];
        float2 v1 = *(float2*)&sm[(r0l + 8) * EPAD + c];
        eacc[j][0] = v0.x; eacc[j][1] = v0.y;
        eacc[j][2] = v1.x; eacc[j][3] = v1.y;
    }

    const int r0 = bm + r0l;

    float ss0 = 0.0f, ss1 = 0.0f;
    #pragma unroll
    for (int j = 0; j < 16; j++) {
        int c = j * 8 + 2 * q;
        float s0 = __ldg(&scale[bn + c]);
        float s1 = __ldg(&scale[bn + c + 1]);
        eacc[j][0] *= s0; eacc[j][1] *= s1;
        eacc[j][2] *= s0; eacc[j][3] *= s1;
        ss0 += eacc[j][0] * eacc[j][0] + eacc[j][1] * eacc[j][1];
        ss1 += eacc[j][2] * eacc[j][2] + eacc[j][3] * eacc[j][3];
    }

    const int b = r0 >> 11;
    const int s0 = r0 & 2047;
    const int s1 = s0 + 8;
    size_t base0 = ((size_t)(b * nheads + h) * S_ + s0) * HD_;
    size_t base1 = ((size_t)(b * nheads + h) * S_ + s1) * HD_;

    if (mode == 2) {                        // V: plain fp16 convert
        #pragma unroll
        for (int j = 0; j < 16; j++) {
            int c = j * 8 + 2 * q;
            *(uint32_t*)&Dst[base0 + c] = packh2(eacc[j][0], eacc[j][1]);
            *(uint32_t*)&Dst[base1 + c] = packh2(eacc[j][2], eacc[j][3]);
        }
        return;
    }

    // Q/K: RMSNorm + RoPE (Q additionally pre-scaled by log2e/sqrt(HD))
    ss0 += __shfl_xor_sync(0xffffffffu, ss0, 1);
    ss0 += __shfl_xor_sync(0xffffffffu, ss0, 2);
    ss1 += __shfl_xor_sync(0xffffffffu, ss1, 1);
    ss1 += __shfl_xor_sync(0xffffffffu, ss1, 2);
    float rms0 = rsqrtf(ss0 * (1.0f / HD_) + EPS_);
    float rms1 = rsqrtf(ss1 * (1.0f / HD_) + EPS_);
    if (mode == 0) { rms0 *= SC_ * LOG2E_; rms1 *= SC_ * LOG2E_; }

    #pragma unroll
    for (int j = 0; j < 8; j++) {
        int c = j * 8 + 2 * q;
        int cp = c + 64;
        float w0a = __ldg(&nw[c]),  w0b = __ldg(&nw[c + 1]);
        float wpa = __ldg(&nw[cp]), wpb = __ldg(&nw[cp + 1]);
        float2 c0 = *(const float2*)&cosc[(size_t)s0 * HD_ + c];
        float2 n0 = *(const float2*)&sinc[(size_t)s0 * HD_ + c];
        float2 c1 = *(const float2*)&cosc[(size_t)s1 * HD_ + c];
        float2 n1 = *(const float2*)&sinc[(size_t)s1 * HD_ + c];

        float xa = eacc[j][0] * rms0 * w0a,     xb = eacc[j][1] * rms0 * w0b;
        float ya = eacc[j + 8][0] * rms0 * wpa, yb = eacc[j + 8][1] * rms0 * wpb;
        *(uint32_t*)&Dst[base0 + c]  = packh2(xa * c0.x - ya * n0.x, xb * c0.y - yb * n0.y);
        *(uint32_t*)&Dst[base0 + cp] = packh2(ya * c0.x + xa * n0.x, yb * c0.y + xb * n0.y);

        xa = eacc[j][2] * rms1 * w0a;     xb = eacc[j][3] * rms1 * w0b;
        ya = eacc[j + 8][2] * rms1 * wpa; yb = eacc[j + 8][3] * rms1 * wpb;
        *(uint32_t*)&Dst[base1 + c]  = packh2(xa * c1.x - ya * n1.x, xb * c1.y - yb * n1.y);
        *(uint32_t*)&Dst[base1 + cp] = packh2(ya * c1.x + xa * n1.x, yb * c1.y + xb * n1.y);
    }
}

// ---------------- O projection kernel (direct fp32 store) ----------------
__global__ __launch_bounds__(256, 2)
void gemm_o(const __half* __restrict__ A, const __half* __restrict__ W,
            const float* __restrict__ scale, float* __restrict__ C, int N) {
    extern __shared__ char dyns[];
    uint32_t tbase = (smem_u32(dyns) + 1023) & ~1023u;

    const int tid = threadIdx.x;
    const int wid = tid >> 5;
    const int L = tid & 31;
    const int bm = blockIdx.y * 128;
    const int bn = blockIdx.x * 128;
    const int wm = (wid & 3) * 32;
    const int wn = (wid >> 2) * 64;

    float acc[2][8][4] = {};
    mma_mainloop(A, W, tbase, bm, bn, tid, acc);

    const int g = L >> 2;
    const int q = L & 3;
    #pragma unroll
    for (int mi = 0; mi < 2; mi++) {
        #pragma unroll
        for (int j = 0; j < 8; j++) {
            int col = bn + wn + j * 8 + q * 2;
            float s0 = __ldg(&scale[col]);
            float s1 = __ldg(&scale[col + 1]);
            int r0 = bm + wm + mi * 16 + g;
            *(float2*)&C[(size_t)r0 * N + col] =
                make_float2(acc[mi][j][0] * s0, acc[mi][j][1] * s1);
            *(float2*)&C[(size_t)(r0 + 8) * N + col] =
                make_float2(acc[mi][j][2] * s0, acc[mi][j][3] * s1);
        }
    }
}

// ---------------- fp16 tensor-core flash attention (causal, GQA) -----------
// logits already in log2 domain (Q pre-scaled by log2e/sqrt(HD))
#define BQA 128
#define BKVA 64
#define AQ_BYTES   32768
#define AKV_STAGE  32768
#define AKV_STG    3
#define ASMEM (AQ_BYTES + AKV_STG * AKV_STAGE)   // 128KB

__device__ __forceinline__ void a_load_kv(uint32_t kvbase, int buf, int kt, int nkv,
                                          size_t kvoff, int tid) {
    if (kt < nkv) {
        int k0 = kt * BKVA;
        uint32_t st = kvbase + buf * AKV_STAGE;
        #pragma unroll
        for (int t = 0; t < 4; t++) {
            int idx = tid + t * 256;
            int row = idx >> 4;
            int ch = idx & 15;
            uint32_t off = sw256((uint32_t)(row * 256 + ch * 16));
            size_t gi = kvoff + (size_t)(k0 + row) * HD_ + ch * 8;
            cp16(st + off,         g_K16 + gi);
            cp16(st + 16384 + off, g_V16 + gi);
        }
    }
    CP_COMMIT();
}

__global__ __launch_bounds__(256, 1)
void attn_mma() {
    extern __shared__ char smraw[];
    uint32_t sb = smem_u32(smraw);
    const int tid = threadIdx.x;
    const int wid = tid >> 5;
    const int L = tid & 31;
    const int g = L >> 2;
    const int qd = L & 3;

    const int qt = (int)gridDim.x - 1 - (int)blockIdx.x;
    const int bh = blockIdx.y;
    const int b = bh >> 4;
    const int h = bh & 15;
    const int kvh = h >> 1;
    const int q0 = qt * BQA;
    const int nkv = 2 * qt + 2;
    const int wm = wid * 16;

    const uint32_t Q_s = sb;
    const uint32_t kvbase = sb + AQ_BYTES;

    const __half* Qg = g_Q16 + ((size_t)bh * S_ + q0) * HD_;
    const size_t kvoff = (size_t)(b * KVH_ + kvh) * S_ * HD_;

    #pragma unroll
    for (int t = 0; t < 8; t++) {
        int idx = tid + t * 256;
        int row = idx >> 4;
        int ch = idx & 15;
        uint32_t off = sw256((uint32_t)(row * 256 + ch * 16));
        cp16(Q_s + off, Qg + (size_t)row * HD_ + ch * 8);
    }
    a_load_kv(kvbase, 0, 0, nkv, kvoff, tid);   // group0 = Q + KV0
    a_load_kv(kvbase, 1, 1, nkv, kvoff, tid);   // group1 = KV1
    a_load_kv(kvbase, 2, 2, nkv, kvoff, tid);   // group2 = KV2

    // hoist Q fragments into registers
    CP_WAIT(2);
    __syncthreads();
    uint32_t qf[8][4];
    {
        const uint32_t a_part = (uint32_t)((L & 15) * 256 + ((L >> 4) << 4));
        #pragma unroll
        for (int k16 = 0; k16 < 8; k16++)
            ldm4(qf[k16], Q_s + sw256((uint32_t)(wm * 256 + k16 * 32) + a_part));
    }

    float m0 = -1e30f, m1 = -1e30f, l0 = 0.0f, l1 = 0.0f;
    float oa[16][4] = {};

    int buf = 0;
    for (int kt = 0; kt < nkv; kt++) {
        CP_WAIT(2);
        __syncthreads();
        const int k0 = kt * BKVA;
        if (k0 <= q0 + wm + 15) {
            uint32_t st = kvbase + buf * AKV_STAGE;
            uint32_t Kh = st, Vh = st + 16384;

            float sa[8][4] = {};
            const uint32_t b_row  = (uint32_t)((L & 7) + ((L >> 4) << 3));
            const uint32_t b_kb   = (uint32_t)(((L >> 3) & 1) * 16);
            #pragma unroll
            for (int k16 = 0; k16 < 8; k16++) {
                #pragma unroll
                for (int n16 = 0; n16 < 4; n16++) {
                    uint32_t boff = sw256((uint32_t)((n16 * 16 + b_row) * 256 + k16 * 32 + b_kb));
                    uint32_t kh4[4];
                    ldm4(kh4, Kh + boff);
                    mma16816(sa[n16 * 2],     qf[k16], &kh4[0]);
                    mma16816(sa[n16 * 2 + 1], qf[k16], &kh4[2]);
                }
            }

            const int r0 = q0 + wm + g;
            const int r1 = r0 + 8;
            if (k0 + 63 > q0 + wm) {
                #pragma unroll
                for (int t = 0; t < 8; t++) {
                    #pragma unroll
                    for (int c = 0; c < 4; c++) {
                        int col = k0 + t * 8 + 2 * qd + (c & 1);
                        int row = (c < 2) ? r0 : r1;
                        if (col > row) sa[t][c] = -1e30f;
                    }
                }
            }

            float mx0 = -1e30f, mx1 = -1e30f;
            #pragma unroll
            for (int t = 0; t < 8; t++) {
                mx0 = fmaxf(mx0, fmaxf(sa[t][0], sa[t][1]));
                mx1 = fmaxf(mx1, fmaxf(sa[t][2], sa[t][3]));
            }
            mx0 = fmaxf(mx0, __shfl_xor_sync(0xffffffffu, mx0, 1));
            mx0 = fmaxf(mx0, __shfl_xor_sync(0xffffffffu, mx0, 2));
            mx1 = fmaxf(mx1, __shfl_xor_sync(0xffffffffu, mx1, 1));
            mx1 = fmaxf(mx1, __shfl_xor_sync(0xffffffffu, mx1, 2));
            float nm0 = fmaxf(m0, mx0), nm1 = fmaxf(m1, mx1);
            float al0 = ex2(m0 - nm0), al1 = ex2(m1 - nm1);
            m0 = nm0; m1 = nm1;
            float rs0 = 0.0f, rs1 = 0.0f;
            #pragma unroll
            for (int t = 0; t < 8; t++) {
                float p0 = ex2(sa[t][0] - m0);
                float p1 = ex2(sa[t][1] - m0);
                float p2 = ex2(sa[t][2] - m1);
                float p3 = ex2(sa[t][3] - m1);
                sa[t][0] = p0; sa[t][1] = p1; sa[t][2] = p2; sa[t][3] = p3;
                rs0 += p0 + p1; rs1 += p2 + p3;
            }
            rs0 += __shfl_xor_sync(0xffffffffu, rs0, 1);
            rs0 += __shfl_xor_sync(0xffffffffu, rs0, 2);
            rs1 += __shfl_xor_sync(0xffffffffu, rs1, 1);
            rs1 += __shfl_xor_sync(0xffffffffu, rs1, 2);
            l0 = l0 * al0 + rs0;
            l1 = l1 * al1 + rs1;
            #pragma unroll
            for (int nt = 0; nt < 16; nt++) {
                oa[nt][0] *= al0; oa[nt][1] *= al0;
                oa[nt][2] *= al1; oa[nt][3] *= al1;
            }

            const uint32_t v_row = (uint32_t)((L & 7) + ((L >> 3) & 1) * 8);
            const uint32_t v_cb  = (uint32_t)((L >> 4) << 4);
            #pragma unroll
            for (int kk = 0; kk < 4; kk++) {
                const int t0 = 2 * kk, t1 = t0 + 1;
                uint32_t ph[4];
                ph[0] = packh2(sa[t0][0], sa[t0][1]);
                ph[1] = packh2(sa[t0][2], sa[t0][3]);
                ph[2] = packh2(sa[t1][0], sa[t1][1]);
                ph[3] = packh2(sa[t1][2], sa[t1][3]);
                #pragma unroll
                for (int n16 = 0; n16 < 8; n16++) {
                    uint32_t voff = sw256((uint32_t)((kk * 16 + v_row) * 256 + n16 * 32) + v_cb);
                    uint32_t vh4[4];
                    ldm4t(vh4, Vh + voff);
                    mma16816(oa[n16 * 2],     ph, &vh4[0]);
                    mma16816(oa[n16 * 2 + 1], ph, &vh4[2]);
                }
            }
        }
        __syncthreads();
        a_load_kv(kvbase, buf, kt + AKV_STG, nkv, kvoff, tid);
        buf++; if (buf >= AKV_STG) buf = 0;
    }

    float inv0 = 1.0f / l0, inv1 = 1.0f / l1;
    const int r0 = q0 + wm + g;
    const int r1 = r0 + 8;
    size_t base0 = ((size_t)(b * S_) + r0) * NQ_ + h * HD_;
    size_t base1 = ((size_t)(b * S_) + r1) * NQ_ + h * HD_;
    #pragma unroll
    for (int nt = 0; nt < 16; nt++) {
        int c = nt * 8 + 2 * qd;
        *(uint32_t*)&g_a16[base0 + c] = packh2(oa[nt][0] * inv0, oa[nt][1] * inv0);
        *(uint32_t*)&g_a16[base1 + c] = packh2(oa[nt][2] * inv1, oa[nt][3] * inv1);
    }
}

// ---------------- launch ----------------
extern "C" void kernel_launch(void* const* d_in, const int* in_sizes, int n_in,
                              void* d_out, int out_size) {
    const float* x    = (const float*)d_in[0];
    const int*   wq   = (const int*)  d_in[1];
    const float* wqs  = (const float*)d_in[2];
    const int*   wk   = (const int*)  d_in[3];
    const float* wks  = (const float*)d_in[4];
    const int*   wv   = (const int*)  d_in[5];
    const float* wvs  = (const float*)d_in[6];
    const int*   wo   = (const int*)  d_in[7];
    const float* wos  = (const float*)d_in[8];
    const float* qnw  = (const float*)d_in[9];
    const float* knw  = (const float*)d_in[10];
    const float* cosc = (const float*)d_in[11];
    const float* sinc = (const float*)d_in[12];
    float* out = (float*)d_out;

    __half *x16, *a16, *wq16, *wk16, *wv16, *wo16, *Q16, *K16, *V16;
    cudaGetSymbolAddress((void**)&x16,  g_x16);
    cudaGetSymbolAddress((void**)&a16,  g_a16);
    cudaGetSymbolAddress((void**)&wq16, g_wq16);
    cudaGetSymbolAddress((void**)&wk16, g_wk16);
    cudaGetSymbolAddress((void**)&wv16, g_wv16);
    cudaGetSymbolAddress((void**)&wo16, g_wo16);
    cudaGetSymbolAddress((void**)&Q16,  g_Q16);
    cudaGetSymbolAddress((void**)&K16,  g_K16);
    cudaGetSymbolAddress((void**)&V16,  g_V16);

    cvt_all<<<(UX + 2 * UQ + 2 * UK) / 256, 256>>>(x, wq, wk, wv, wo);

    cudaFuncSetAttribute(gemm_qkv, cudaFuncAttributeMaxDynamicSharedMemorySize, GSMEM_DYN);
    cudaFuncSetAttribute(gemm_o,   cudaFuncAttributeMaxDynamicSharedMemorySize, GSMEM_DYN);

    gemm_qkv<<<dim3(32, M_ / 128), 256, GSMEM_DYN>>>(
        x16, wq16, wk16, wv16, wqs, wks, wvs, qnw, knw, cosc, sinc, Q16, K16, V16);

    cudaFuncSetAttribute(attn_mma, cudaFuncAttributeMaxDynamicSharedMemorySize, ASMEM);
    attn_mma<<<dim3(S_ / BQA, B_ * H_), 256, ASMEM>>>();

    gemm_o<<<dim3(D_ / 128, M_ / 128), 256, GSMEM_DYN>>>(a16, wo16, wos, out, D_);
}

// round 11
// speedup vs baseline: 4.9870x; 1.0430x over previous
#include <cuda_runtime.h>
#include <cuda_fp16.h>
#include <math.h>
#include <stdint.h>

#define B_   2
#define S_   2048
#define D_   2048
#define H_   16
#define KVH_ 8
#define HD_  128
#define M_   (B_ * S_)          // 4096
#define NQ_  (H_ * HD_)         // 2048
#define NKV_ (KVH_ * HD_)       // 1024
#define EPS_ 1e-6f
#define SC_    0.08838834764831845f    // 1/sqrt(128)
#define LOG2E_ 1.4426950408889634f

// ---------------- scratch (device globals, allocation-free) ----------------
__device__ __align__(256) __half g_x16[M_ * D_];
__device__ __align__(256) __half g_a16[M_ * NQ_];
__device__ __align__(256) __half g_wq16[NQ_ * D_];
__device__ __align__(256) __half g_wk16[NKV_ * D_];
__device__ __align__(256) __half g_wv16[NKV_ * D_];
__device__ __align__(256) __half g_wo16[D_ * NQ_];
__device__ __align__(256) __half g_Q16[M_ * NQ_];
__device__ __align__(256) __half g_K16[M_ * NKV_];
__device__ __align__(256) __half g_V16[M_ * NKV_];

// ---------------- PTX helpers (baseline PTX only) ----------------
__device__ __forceinline__ uint32_t smem_u32(const void* p) {
    uint32_t a;
    asm("{ .reg .u64 t; cvta.to.shared.u64 t, %1; cvt.u32.u64 %0, t; }" : "=r"(a) : "l"(p));
    return a;
}
__device__ __forceinline__ void cp16(uint32_t s, const void* g) {
    asm volatile("cp.async.cg.shared.global [%0], [%1], 16;" :: "r"(s), "l"(g));
}
#define CP_COMMIT() asm volatile("cp.async.commit_group;" ::: "memory")
#define CP_WAIT(n)  asm volatile("cp.async.wait_group %0;" :: "n"(n) : "memory")

__device__ __forceinline__ void ldm4(uint32_t* r, uint32_t addr) {
    asm volatile("ldmatrix.sync.aligned.m8n8.x4.shared.b16 {%0,%1,%2,%3}, [%4];"
                 : "=r"(r[0]), "=r"(r[1]), "=r"(r[2]), "=r"(r[3]) : "r"(addr));
}
__device__ __forceinline__ void ldm4t(uint32_t* r, uint32_t addr) {
    asm volatile("ldmatrix.sync.aligned.m8n8.x4.trans.shared.b16 {%0,%1,%2,%3}, [%4];"
                 : "=r"(r[0]), "=r"(r[1]), "=r"(r[2]), "=r"(r[3]) : "r"(addr));
}
__device__ __forceinline__ void mma16816(float* c, const uint32_t* a, const uint32_t* b) {
    asm volatile("mma.sync.aligned.m16n8k16.row.col.f32.f16.f16.f32 "
                 "{%0,%1,%2,%3}, {%4,%5,%6,%7}, {%8,%9}, {%0,%1,%2,%3};"
                 : "+f"(c[0]), "+f"(c[1]), "+f"(c[2]), "+f"(c[3])
                 : "r"(a[0]), "r"(a[1]), "r"(a[2]), "r"(a[3]), "r"(b[0]), "r"(b[1]));
}

__device__ __forceinline__ uint32_t sw128(uint32_t off) { return off ^ ((off >> 3) & 0x70); }
__device__ __forceinline__ uint32_t sw256(uint32_t off) { return off ^ ((off >> 4) & 0x70); }

__device__ __forceinline__ uint32_t packh2(float a, float b) {
    __half2 h = __floats2half2_rn(a, b);
    return *(uint32_t*)&h;
}
__device__ __forceinline__ float ex2(float x) {
    float y;
    asm("ex2.approx.f32 %0, %1;" : "=f"(y) : "f"(x));
    return y;
}

// ---------------- merged conversion kernel ----------------
#define UX (M_ * D_ / 4)
#define UQ (NQ_ * D_ / 4)
#define UK (NKV_ * D_ / 4)
__global__ void cvt_all(const float* __restrict__ x,
                        const int* __restrict__ wq, const int* __restrict__ wk,
                        const int* __restrict__ wv, const int* __restrict__ wo) {
    int i = blockIdx.x * blockDim.x + threadIdx.x;
    if (i < UX) {
        float4 v = ((const float4*)x)[i];
        uint2 p;
        p.x = packh2(v.x, v.y);
        p.y = packh2(v.z, v.w);
        ((uint2*)g_x16)[i] = p;
        return;
    }
    i -= UX;
    const int* src;
    __half* dst;
    int k;
    if (i < UQ)                    { src = wq; dst = g_wq16; k = i; }
    else if (i < UQ + UK)          { src = wk; dst = g_wk16; k = i - UQ; }
    else if (i < UQ + 2 * UK)      { src = wv; dst = g_wv16; k = i - UQ - UK; }
    else                           { src = wo; dst = g_wo16; k = i - UQ - 2 * UK; }
    int4 v = ((const int4*)src)[k];
    uint2 p;
    p.x = packh2((float)v.x, (float)v.y);
    p.y = packh2((float)v.z, (float)v.w);
    ((uint2*)dst)[k] = p;
}

// ---------------- shared GEMM mainloop (32x64 warp tiles, fp16) -----------
#define GBK       64
#define GCHUNK    (D_ / GBK)          // 32
#define GTILE_B   16384               // 128 rows x 128B
#define GSTAGE_B  (2 * GTILE_B)       // A, W
#define GSTG      3
#define GSMEM_DYN (GSTG * GSTAGE_B + 1024)
#define EPAD      132

__device__ __forceinline__ void g_load_chunk(
    uint32_t tbase, int buf, int kc,
    const __half* __restrict__ A, const __half* __restrict__ W,
    int bm, int bn, int tid) {
    uint32_t st = tbase + buf * GSTAGE_B;
    const __half* Ap = A + (size_t)bm * D_ + kc * GBK;
    const __half* Wp = W + (size_t)bn * D_ + kc * GBK;
    #pragma unroll
    for (int t = 0; t < 4; t++) {
        int idx = tid + t * 256;
        int row = idx >> 3;
        int seg = idx & 7;
        uint32_t off = sw128((uint32_t)(row * 128 + seg * 16));
        size_t gofs = (size_t)row * D_ + seg * 8;
        cp16(st + off,           Ap + gofs);
        cp16(st + GTILE_B + off, Wp + gofs);
    }
    CP_COMMIT();
}

__device__ __forceinline__ void mma_mainloop(
    const __half* __restrict__ A, const __half* __restrict__ W,
    uint32_t tbase, int bm, int bn, int tid, float acc[2][8][4]) {
    const int wid = tid >> 5;
    const int L = tid & 31;
    const int wm = (wid & 3) * 32;
    const int wn = (wid >> 2) * 64;

    g_load_chunk(tbase, 0, 0, A, W, bm, bn, tid);
    g_load_chunk(tbase, 1, 1, A, W, bm, bn, tid);

    const int a_row = (L & 7) + ((L >> 3) & 1) * 8;
    const int a_kb  = (L >> 4) * 16;
    const int b_row = (L & 7) + ((L >> 4) << 3);
    const int b_kb  = ((L >> 3) & 1) * 16;

    int buf = 0;
    for (int kc = 0; kc < GCHUNK; kc++) {
        CP_WAIT(1);
        __syncthreads();
        if (kc + 2 < GCHUNK) {
            int nb = buf + 2; if (nb >= GSTG) nb -= GSTG;
            g_load_chunk(tbase, nb, kc + 2, A, W, bm, bn, tid);
        } else {
            CP_COMMIT();
        }

        uint32_t st = tbase + buf * GSTAGE_B;
        #pragma unroll
        for (int ks = 0; ks < 4; ks++) {
            uint32_t ah[2][4], bb[4][4];
            #pragma unroll
            for (int mi = 0; mi < 2; mi++) {
                uint32_t off = sw128((uint32_t)((wm + mi * 16 + a_row) * 128 + ks * 32 + a_kb));
                ldm4(ah[mi], st + off);
            }
            #pragma unroll
            for (int nj = 0; nj < 4; nj++) {
                uint32_t off = sw128((uint32_t)((wn + nj * 16 + b_row) * 128 + ks * 32 + b_kb));
                ldm4(bb[nj], st + GTILE_B + off);
            }
            #pragma unroll
            for (int mi = 0; mi < 2; mi++)
                #pragma unroll
                for (int j = 0; j < 8; j++)
                    mma16816(acc[mi][j], ah[mi], &bb[j >> 1][(j & 1) * 2]);
        }
        buf++; if (buf >= GSTG) buf = 0;
    }
}

// ---------------- fused QKV projection kernel ----------------
__global__ __launch_bounds__(256, 2)
void gemm_qkv(const __half* __restrict__ A,
              const __half* __restrict__ Wq, const __half* __restrict__ Wk,
              const __half* __restrict__ Wv,
              const float* __restrict__ sq, const float* __restrict__ sk,
              const float* __restrict__ sv,
              const float* __restrict__ qnw, const float* __restrict__ knw,
              const float* __restrict__ cosc, const float* __restrict__ sinc,
              __half* __restrict__ Q, __half* __restrict__ K, __half* __restrict__ V) {
    extern __shared__ char dyns[];
    uint32_t tbase = (smem_u32(dyns) + 1023) & ~1023u;

    const int tid = threadIdx.x;
    const int wid = tid >> 5;
    const int L = tid & 31;
    const int bx = blockIdx.x;
    const int bm = blockIdx.y * 128;

    const __half* W;
    const float* scale;
    const float* nw;
    __half* Dst;
    int mode, h, nheads;
    if (bx < 16)      { W = Wq; scale = sq; nw = qnw; Dst = Q; mode = 0; h = bx;      nheads = H_;  }
    else if (bx < 24) { W = Wk; scale = sk; nw = knw; Dst = K; mode = 1; h = bx - 16; nheads = KVH_; }
    else              { W = Wv; scale = sv; nw = knw; Dst = V; mode = 2; h = bx - 24; nheads = KVH_; }
    const int bn = h * 128;

    float acc[2][8][4] = {};
    mma_mainloop(A, W, tbase, bm, bn, tid, acc);

    // epilogue: exchange acc through smem into row-major per-warp layout
    float* sm = (float*)dyns;
    const int g = L >> 2;
    const int q = L & 3;
    {
        const int wm = (wid & 3) * 32;
        const int wn = (wid >> 2) * 64;
        __syncthreads();
        #pragma unroll
        for (int mi = 0; mi < 2; mi++) {
            int row = wm + mi * 16 + g;
            #pragma unroll
            for (int j = 0; j < 8; j++) {
                int col = wn + j * 8 + 2 * q;
                *(float2*)&sm[row * EPAD + col] = make_float2(acc[mi][j][0], acc[mi][j][1]);
                *(float2*)&sm[(row + 8) * EPAD + col] = make_float2(acc[mi][j][2], acc[mi][j][3]);
            }
        }
        __syncthreads();
    }

    float eacc[16][4];
    const int r0l = wid * 16 + g;
    #pragma unroll
    for (int j = 0; j < 16; j++) {
        int c = j * 8 + 2 * q;
        float2 v0 = *(float2*)&sm[r0l * EPAD + c];
        float2 v1 = *(float2*)&sm[(r0l + 8) * EPAD + c];
        eacc[j][0] = v0.x; eacc[j][1] = v0.y;
        eacc[j][2] = v1.x; eacc[j][3] = v1.y;
    }

    const int r0 = bm + r0l;

    float ss0 = 0.0f, ss1 = 0.0f;
    #pragma unroll
    for (int j = 0; j < 16; j++) {
        int c = j * 8 + 2 * q;
        float s0 = __ldg(&scale[bn + c]);
        float s1 = __ldg(&scale[bn + c + 1]);
        eacc[j][0] *= s0; eacc[j][1] *= s1;
        eacc[j][2] *= s0; eacc[j][3] *= s1;
        ss0 += eacc[j][0] * eacc[j][0] + eacc[j][1] * eacc[j][1];
        ss1 += eacc[j][2] * eacc[j][2] + eacc[j][3] * eacc[j][3];
    }

    const int b = r0 >> 11;
    const int s0 = r0 & 2047;
    const int s1 = s0 + 8;
    size_t base0 = ((size_t)(b * nheads + h) * S_ + s0) * HD_;
    size_t base1 = ((size_t)(b * nheads + h) * S_ + s1) * HD_;

    if (mode == 2) {                        // V: plain fp16 convert
        #pragma unroll
        for (int j = 0; j < 16; j++) {
            int c = j * 8 + 2 * q;
            *(uint32_t*)&Dst[base0 + c] = packh2(eacc[j][0], eacc[j][1]);
            *(uint32_t*)&Dst[base1 + c] = packh2(eacc[j][2], eacc[j][3]);
        }
        return;
    }

    // Q/K: RMSNorm + RoPE (Q additionally pre-scaled by log2e/sqrt(HD))
    ss0 += __shfl_xor_sync(0xffffffffu, ss0, 1);
    ss0 += __shfl_xor_sync(0xffffffffu, ss0, 2);
    ss1 += __shfl_xor_sync(0xffffffffu, ss1, 1);
    ss1 += __shfl_xor_sync(0xffffffffu, ss1, 2);
    float rms0 = rsqrtf(ss0 * (1.0f / HD_) + EPS_);
    float rms1 = rsqrtf(ss1 * (1.0f / HD_) + EPS_);
    if (mode == 0) { rms0 *= SC_ * LOG2E_; rms1 *= SC_ * LOG2E_; }

    #pragma unroll
    for (int j = 0; j < 8; j++) {
        int c = j * 8 + 2 * q;
        int cp = c + 64;
        float w0a = __ldg(&nw[c]),  w0b = __ldg(&nw[c + 1]);
        float wpa = __ldg(&nw[cp]), wpb = __ldg(&nw[cp + 1]);
        float2 c0 = *(const float2*)&cosc[(size_t)s0 * HD_ + c];
        float2 n0 = *(const float2*)&sinc[(size_t)s0 * HD_ + c];
        float2 c1 = *(const float2*)&cosc[(size_t)s1 * HD_ + c];
        float2 n1 = *(const float2*)&sinc[(size_t)s1 * HD_ + c];

        float xa = eacc[j][0] * rms0 * w0a,     xb = eacc[j][1] * rms0 * w0b;
        float ya = eacc[j + 8][0] * rms0 * wpa, yb = eacc[j + 8][1] * rms0 * wpb;
        *(uint32_t*)&Dst[base0 + c]  = packh2(xa * c0.x - ya * n0.x, xb * c0.y - yb * n0.y);
        *(uint32_t*)&Dst[base0 + cp] = packh2(ya * c0.x + xa * n0.x, yb * c0.y + xb * n0.y);

        xa = eacc[j][2] * rms1 * w0a;     xb = eacc[j][3] * rms1 * w0b;
        ya = eacc[j + 8][2] * rms1 * wpa; yb = eacc[j + 8][3] * rms1 * wpb;
        *(uint32_t*)&Dst[base1 + c]  = packh2(xa * c1.x - ya * n1.x, xb * c1.y - yb * n1.y);
        *(uint32_t*)&Dst[base1 + cp] = packh2(ya * c1.x + xa * n1.x, yb * c1.y + xb * n1.y);
    }
}

// ---------------- O projection kernel (direct fp32 store) ----------------
__global__ __launch_bounds__(256, 2)
void gemm_o(const __half* __restrict__ A, const __half* __restrict__ W,
            const float* __restrict__ scale, float* __restrict__ C, int N) {
    extern __shared__ char dyns[];
    uint32_t tbase = (smem_u32(dyns) + 1023) & ~1023u;

    const int tid = threadIdx.x;
    const int wid = tid >> 5;
    const int L = tid & 31;
    const int bm = blockIdx.y * 128;
    const int bn = blockIdx.x * 128;
    const int wm = (wid & 3) * 32;
    const int wn = (wid >> 2) * 64;

    float acc[2][8][4] = {};
    mma_mainloop(A, W, tbase, bm, bn, tid, acc);

    const int g = L >> 2;
    const int q = L & 3;
    #pragma unroll
    for (int mi = 0; mi < 2; mi++) {
        #pragma unroll
        for (int j = 0; j < 8; j++) {
            int col = bn + wn + j * 8 + q * 2;
            float s0 = __ldg(&scale[col]);
            float s1 = __ldg(&scale[col + 1]);
            int r0 = bm + wm + mi * 16 + g;
            *(float2*)&C[(size_t)r0 * N + col] =
                make_float2(acc[mi][j][0] * s0, acc[mi][j][1] * s1);
            *(float2*)&C[(size_t)(r0 + 8) * N + col] =
                make_float2(acc[mi][j][2] * s0, acc[mi][j][3] * s1);
        }
    }
}

// ---------------- fp16 tensor-core flash attention (causal, GQA) -----------
// 64-row q tiles, 128 threads (4 warps), 2 CTAs/SM for phase overlap.
// logits already in log2 domain (Q pre-scaled by log2e/sqrt(HD))
#define BQA 64
#define BKVA 64
#define ATHREADS   128
#define AQ_BYTES   16384        // 64 rows x 256B
#define AKV_STAGE  32768        // K 16KB + V 16KB
#define AKV_STG    3
#define ASMEM (AQ_BYTES + AKV_STG * AKV_STAGE)   // 112KB

__device__ __forceinline__ void a_load_kv(uint32_t kvbase, int buf, int kt, int nkv,
                                          size_t kvoff, int tid) {
    if (kt < nkv) {
        int k0 = kt * BKVA;
        uint32_t st = kvbase + buf * AKV_STAGE;
        #pragma unroll
        for (int t = 0; t < 8; t++) {
            int idx = tid + t * ATHREADS;     // 0..1023
            int row = idx >> 4;               // 0..63
            int ch = idx & 15;
            uint32_t off = sw256((uint32_t)(row * 256 + ch * 16));
            size_t gi = kvoff + (size_t)(k0 + row) * HD_ + ch * 8;
            cp16(st + off,         g_K16 + gi);
            cp16(st + 16384 + off, g_V16 + gi);
        }
    }
    CP_COMMIT();
}

__global__ __launch_bounds__(ATHREADS, 2)
void attn_mma() {
    extern __shared__ char smraw[];
    uint32_t sb = smem_u32(smraw);
    const int tid = threadIdx.x;
    const int wid = tid >> 5;                 // 0..3
    const int L = tid & 31;
    const int g = L >> 2;
    const int qd = L & 3;

    const int qt = (int)gridDim.x - 1 - (int)blockIdx.x;   // heavy tiles first
    const int bh = blockIdx.y;
    const int b = bh >> 4;
    const int h = bh & 15;
    const int kvh = h >> 1;
    const int q0 = qt * BQA;
    const int nkv = qt + 1;
    const int wm = wid * 16;

    const uint32_t Q_s = sb;
    const uint32_t kvbase = sb + AQ_BYTES;

    const __half* Qg = g_Q16 + ((size_t)bh * S_ + q0) * HD_;
    const size_t kvoff = (size_t)(b * KVH_ + kvh) * S_ * HD_;

    // group0 = Q + KV0
    #pragma unroll
    for (int t = 0; t < 8; t++) {
        int idx = tid + t * ATHREADS;         // 0..1023
        int row = idx >> 4;                   // 0..63
        int ch = idx & 15;
        uint32_t off = sw256((uint32_t)(row * 256 + ch * 16));
        cp16(Q_s + off, Qg + (size_t)row * HD_ + ch * 8);
    }
    a_load_kv(kvbase, 0, 0, nkv, kvoff, tid);
    a_load_kv(kvbase, 1, 1, nkv, kvoff, tid);
    a_load_kv(kvbase, 2, 2, nkv, kvoff, tid);

    // hoist Q fragments into registers
    CP_WAIT(2);
    __syncthreads();
    uint32_t qf[8][4];
    {
        const uint32_t a_part = (uint32_t)((L & 15) * 256 + ((L >> 4) << 4));
        #pragma unroll
        for (int k16 = 0; k16 < 8; k16++)
            ldm4(qf[k16], Q_s + sw256((uint32_t)(wm * 256 + k16 * 32) + a_part));
    }

    float m0 = -1e30f, m1 = -1e30f, l0 = 0.0f, l1 = 0.0f;
    float oa[16][4] = {};

    int buf = 0;
    for (int kt = 0; kt < nkv; kt++) {
        CP_WAIT(2);
        __syncthreads();
        const int k0 = kt * BKVA;
        {
            uint32_t st = kvbase + buf * AKV_STAGE;
            uint32_t Kh = st, Vh = st + 16384;

            float sa[8][4] = {};
            const uint32_t b_row  = (uint32_t)((L & 7) + ((L >> 4) << 3));
            const uint32_t b_kb   = (uint32_t)(((L >> 3) & 1) * 16);
            #pragma unroll
            for (int k16 = 0; k16 < 8; k16++) {
                #pragma unroll
                for (int n16 = 0; n16 < 4; n16++) {
                    uint32_t boff = sw256((uint32_t)((n16 * 16 + b_row) * 256 + k16 * 32 + b_kb));
                    uint32_t kh4[4];
                    ldm4(kh4, Kh + boff);
                    mma16816(sa[n16 * 2],     qf[k16], &kh4[0]);
                    mma16816(sa[n16 * 2 + 1], qf[k16], &kh4[2]);
                }
            }

            const int r0 = q0 + wm + g;
            const int r1 = r0 + 8;
            if (k0 + 63 > q0 + wm) {          // diagonal tile: apply causal mask
                #pragma unroll
                for (int t = 0; t < 8; t++) {
                    #pragma unroll
                    for (int c = 0; c < 4; c++) {
                        int col = k0 + t * 8 + 2 * qd + (c & 1);
                        int row = (c < 2) ? r0 : r1;
                        if (col > row) sa[t][c] = -1e30f;
                    }
                }
            }

            float mx0 = -1e30f, mx1 = -1e30f;
            #pragma unroll
            for (int t = 0; t < 8; t++) {
                mx0 = fmaxf(mx0, fmaxf(sa[t][0], sa[t][1]));
                mx1 = fmaxf(mx1, fmaxf(sa[t][2], sa[t][3]));
            }
            mx0 = fmaxf(mx0, __shfl_xor_sync(0xffffffffu, mx0, 1));
            mx0 = fmaxf(mx0, __shfl_xor_sync(0xffffffffu, mx0, 2));
            mx1 = fmaxf(mx1, __shfl_xor_sync(0xffffffffu, mx1, 1));
            mx1 = fmaxf(mx1, __shfl_xor_sync(0xffffffffu, mx1, 2));
            float nm0 = fmaxf(m0, mx0), nm1 = fmaxf(m1, mx1);
            float al0 = ex2(m0 - nm0), al1 = ex2(m1 - nm1);
            m0 = nm0; m1 = nm1;
            float rs0 = 0.0f, rs1 = 0.0f;
            #pragma unroll
            for (int t = 0; t < 8; t++) {
                float p0 = ex2(sa[t][0] - m0);
                float p1 = ex2(sa[t][1] - m0);
                float p2 = ex2(sa[t][2] - m1);
                float p3 = ex2(sa[t][3] - m1);
                sa[t][0] = p0; sa[t][1] = p1; sa[t][2] = p2; sa[t][3] = p3;
                rs0 += p0 + p1; rs1 += p2 + p3;
            }
            rs0 += __shfl_xor_sync(0xffffffffu, rs0, 1);
            rs0 += __shfl_xor_sync(0xffffffffu, rs0, 2);
            rs1 += __shfl_xor_sync(0xffffffffu, rs1, 1);
            rs1 += __shfl_xor_sync(0xffffffffu, rs1, 2);
            l0 = l0 * al0 + rs0;
            l1 = l1 * al1 + rs1;
            #pragma unroll
            for (int nt = 0; nt < 16; nt++) {
                oa[nt][0] *= al0; oa[nt][1] *= al0;
                oa[nt][2] *= al1; oa[nt][3] *= al1;
            }

            const uint32_t v_row = (uint32_t)((L & 7) + ((L >> 3) & 1) * 8);
            const uint32_t v_cb  = (uint32_t)((L >> 4) << 4);
            #pragma unroll
            for (int kk = 0; kk < 4; kk++) {
                const int t0 = 2 * kk, t1 = t0 + 1;
                uint32_t ph[4];
                ph[0] = packh2(sa[t0][0], sa[t0][1]);
                ph[1] = packh2(sa[t0][2], sa[t0][3]);
                ph[2] = packh2(sa[t1][0], sa[t1][1]);
                ph[3] = packh2(sa[t1][2], sa[t1][3]);
                #pragma unroll
                for (int n16 = 0; n16 < 8; n16++) {
                    uint32_t voff = sw256((uint32_t)((kk * 16 + v_row) * 256 + n16 * 32) + v_cb);
                    uint32_t vh4[4];
                    ldm4t(vh4, Vh + voff);
                    mma16816(oa[n16 * 2],     ph, &vh4[0]);
                    mma16816(oa[n16 * 2 + 1], ph, &vh4[2]);
                }
            }
        }
        __syncthreads();
        a_load_kv(kvbase, buf, kt + AKV_STG, nkv, kvoff, tid);
        buf++; if (buf >= AKV_STG) buf = 0;
    }

    float inv0 = 1.0f / l0, inv1 = 1.0f / l1;
    const int r0 = q0 + wm + g;
    const int r1 = r0 + 8;
    size_t base0 = ((size_t)(b * S_) + r0) * NQ_ + h * HD_;
    size_t base1 = ((size_t)(b * S_) + r1) * NQ_ + h * HD_;
    #pragma unroll
    for (int nt = 0; nt < 16; nt++) {
        int c = nt * 8 + 2 * qd;
        *(uint32_t*)&g_a16[base0 + c] = packh2(oa[nt][0] * inv0, oa[nt][1] * inv0);
        *(uint32_t*)&g_a16[base1 + c] = packh2(oa[nt][2] * inv1, oa[nt][3] * inv1);
    }
}

// ---------------- launch ----------------
extern "C" void kernel_launch(void* const* d_in, const int* in_sizes, int n_in,
                              void* d_out, int out_size) {
    const float* x    = (const float*)d_in[0];
    const int*   wq   = (const int*)  d_in[1];
    const float* wqs  = (const float*)d_in[2];
    const int*   wk   = (const int*)  d_in[3];
    const float* wks  = (const float*)d_in[4];
    const int*   wv   = (const int*)  d_in[5];
    const float* wvs  = (const float*)d_in[6];
    const int*   wo   = (const int*)  d_in[7];
    const float* wos  = (const float*)d_in[8];
    const float* qnw  = (const float*)d_in[9];
    const float* knw  = (const float*)d_in[10];
    const float* cosc = (const float*)d_in[11];
    const float* sinc = (const float*)d_in[12];
    float* out = (float*)d_out;

    __half *x16, *a16, *wq16, *wk16, *wv16, *wo16, *Q16, *K16, *V16;
    cudaGetSymbolAddress((void**)&x16,  g_x16);
    cudaGetSymbolAddress((void**)&a16,  g_a16);
    cudaGetSymbolAddress((void**)&wq16, g_wq16);
    cudaGetSymbolAddress((void**)&wk16, g_wk16);
    cudaGetSymbolAddress((void**)&wv16, g_wv16);
    cudaGetSymbolAddress((void**)&wo16, g_wo16);
    cudaGetSymbolAddress((void**)&Q16,  g_Q16);
    cudaGetSymbolAddress((void**)&K16,  g_K16);
    cudaGetSymbolAddress((void**)&V16,  g_V16);

    cvt_all<<<(UX + 2 * UQ + 2 * UK) / 256, 256>>>(x, wq, wk, wv, wo);

    cudaFuncSetAttribute(gemm_qkv, cudaFuncAttributeMaxDynamicSharedMemorySize, GSMEM_DYN);
    cudaFuncSetAttribute(gemm_o,   cudaFuncAttributeMaxDynamicSharedMemorySize, GSMEM_DYN);

    gemm_qkv<<<dim3(32, M_ / 128), 256, GSMEM_DYN>>>(
        x16, wq16, wk16, wv16, wqs, wks, wvs, qnw, knw, cosc, sinc, Q16, K16, V16);

    cudaFuncSetAttribute(attn_mma, cudaFuncAttributeMaxDynamicSharedMemorySize, ASMEM);
    attn_mma<<<dim3(S_ / BQA, B_ * H_), ATHREADS, ASMEM>>>();

    gemm_o<<<dim3(D_ / 128, M_ / 128), 256, GSMEM_DYN>>>(a16, wo16, wos, out, D_);
}